// round 12
// baseline (speedup 1.0000x reference)
#include <cuda_runtime.h>
#include <cuda_bf16.h>
#include <math_constants.h>
#include <cstdint>

// Problem constants
#define T_DIM 1024
#define B_DIM 4
#define C_DIM 1024
#define H_DIM 16
#define D_DIM 64
#define P_DIM 2047
#define BT_DIM (B_DIM * T_DIM)

// Scratch (device globals). Row order m = t*B + b ([T,B,C] natural).
__device__ __nv_bfloat16 g_quh[BT_DIM * C_DIM];  // (q@Wq+bq+pbu)*0.125 hi
__device__ __nv_bfloat16 g_qul[BT_DIM * C_DIM];  // lo
__device__ __nv_bfloat16 g_kh[BT_DIM * C_DIM];
__device__ __nv_bfloat16 g_kl[BT_DIM * C_DIM];
__device__ __nv_bfloat16 g_vh[BT_DIM * C_DIM];
__device__ __nv_bfloat16 g_vl[BT_DIM * C_DIM];
__device__ __nv_bfloat16 g_ph[P_DIM * C_DIM];
__device__ __nv_bfloat16 g_pl[P_DIM * C_DIM];
__device__ __nv_bfloat16 g_xh[BT_DIM * C_DIM];
__device__ __nv_bfloat16 g_xl[BT_DIM * C_DIM];
// Pre-split GEMM operands
#define OWQ 0
#define OWK 1048576
#define OWV 2097152
#define OWP 3145728
#define OWO 4194304
__device__ __nv_bfloat16 g_wh[5 * 1048576];
__device__ __nv_bfloat16 g_wl[5 * 1048576];
#define OIQ 0
#define OIK 4194304
#define OIV 8388608
#define OIP 12582912
__device__ __nv_bfloat16 g_inh[14679040];
__device__ __nv_bfloat16 g_inl[14679040];

// ---------------------------------------------------------------------------
// Helpers
// ---------------------------------------------------------------------------
__device__ __forceinline__ uint32_t smem_u32(const void* p) {
    uint32_t a;
    asm("{ .reg .u64 t; cvta.to.shared.u64 t, %1; cvt.u32.u64 %0, t; }" : "=r"(a) : "l"(p));
    return a;
}
__device__ __forceinline__ void cp_async16(uint32_t saddr, const void* gptr, bool pred) {
    const int sz = pred ? 16 : 0;
    asm volatile("cp.async.cg.shared.global [%0], [%1], 16, %2;"
                 :: "r"(saddr), "l"(gptr), "r"(sz));
}
__device__ __forceinline__ void cp_commit() { asm volatile("cp.async.commit_group;"); }
template <int N>
__device__ __forceinline__ void cp_wait() { asm volatile("cp.async.wait_group %0;" :: "n"(N)); }

__device__ __forceinline__ void ldsm_x4(uint32_t* r, uint32_t a) {
    asm volatile("ldmatrix.sync.aligned.m8n8.x4.shared.b16 {%0,%1,%2,%3}, [%4];"
                 : "=r"(r[0]), "=r"(r[1]), "=r"(r[2]), "=r"(r[3]) : "r"(a));
}
__device__ __forceinline__ void ldsm_x4t(uint32_t* r, uint32_t a) {
    asm volatile("ldmatrix.sync.aligned.m8n8.x4.trans.shared.b16 {%0,%1,%2,%3}, [%4];"
                 : "=r"(r[0]), "=r"(r[1]), "=r"(r[2]), "=r"(r[3]) : "r"(a));
}
__device__ __forceinline__ void mma_bf16(float* c, const uint32_t* a, const uint32_t* b) {
    asm volatile("mma.sync.aligned.m16n8k16.row.col.f32.bf16.bf16.f32 "
                 "{%0,%1,%2,%3}, {%4,%5,%6,%7}, {%8,%9}, {%0,%1,%2,%3};"
                 : "+f"(c[0]), "+f"(c[1]), "+f"(c[2]), "+f"(c[3])
                 : "r"(a[0]), "r"(a[1]), "r"(a[2]), "r"(a[3]), "r"(b[0]), "r"(b[1]));
}
__device__ __forceinline__ uint32_t us16(__nv_bfloat16 h) { return (uint32_t)__bfloat16_as_ushort(h); }

// Padded-pitch fragment addressing (attention kernel)
__device__ __forceinline__ uint32_t a_addr(uint32_t base, int row0, int k0, int lane, int pitch) {
    const int row = row0 + (lane & 15);
    const int col = k0 + ((lane >> 4) << 3);
    return base + (uint32_t)((row * pitch + col) * 2);
}
__device__ __forceinline__ uint32_t b_addr(uint32_t base, int n0, int k0, int lane, int pitch) {
    const int row = n0 + (lane & 7) + ((lane >> 4) << 3);
    const int col = k0 + (lane & 8);
    return base + (uint32_t)((row * pitch + col) * 2);
}

// Swizzled 64B-row tile addressing (GEMM core): rows x 32 bf16, no padding.
__device__ __forceinline__ uint32_t sw64(int row, int chunk) {
    return (uint32_t)((row << 6) + (((chunk ^ (row >> 1)) & 3) << 4));
}

__device__ __forceinline__ void st_pair_split(__nv_bfloat16* gh, __nv_bfloat16* gl,
                                              size_t off, float x0, float x1) {
    __nv_bfloat16 h0 = __float2bfloat16_rn(x0), h1 = __float2bfloat16_rn(x1);
    __nv_bfloat16 l0 = __float2bfloat16_rn(x0 - __bfloat162float(h0));
    __nv_bfloat16 l1 = __float2bfloat16_rn(x1 - __bfloat162float(h1));
    *(__nv_bfloat162*)(gh + off) = __halves2bfloat162(h0, h1);
    *(__nv_bfloat162*)(gl + off) = __halves2bfloat162(l0, l1);
}

// ---------------------------------------------------------------------------
// Merged setup: split all 9 fp32 arrays -> bf16 hi/lo in ONE launch.
// ---------------------------------------------------------------------------
__global__ void __launch_bounds__(256)
split_all(const float4* __restrict__ Wq, const float4* __restrict__ Wk,
          const float4* __restrict__ Wv, const float4* __restrict__ Wp,
          const float4* __restrict__ Wo,
          const float4* __restrict__ q, const float4* __restrict__ k,
          const float4* __restrict__ v, const float4* __restrict__ p)
{
    const int bid = blockIdx.x;
    const float4* src;
    uint2 *dh, *dl;
    int i, n4;
    if (bid < 5120) {
        const int w = bid >> 10;
        src = (w == 0) ? Wq : (w == 1) ? Wk : (w == 2) ? Wv : (w == 3) ? Wp : Wo;
        dh = (uint2*)(g_wh + w * 1048576);
        dl = (uint2*)(g_wl + w * 1048576);
        i = (bid & 1023) * 256 + threadIdx.x;
        n4 = 262144;
    } else if (bid < 9216) {
        src = q; dh = (uint2*)(g_inh + OIQ); dl = (uint2*)(g_inl + OIQ);
        i = (bid - 5120) * 256 + threadIdx.x; n4 = 1048576;
    } else if (bid < 13312) {
        src = k; dh = (uint2*)(g_inh + OIK); dl = (uint2*)(g_inl + OIK);
        i = (bid - 9216) * 256 + threadIdx.x; n4 = 1048576;
    } else if (bid < 17408) {
        src = v; dh = (uint2*)(g_inh + OIV); dl = (uint2*)(g_inl + OIV);
        i = (bid - 13312) * 256 + threadIdx.x; n4 = 1048576;
    } else {
        src = p; dh = (uint2*)(g_inh + OIP); dl = (uint2*)(g_inl + OIP);
        i = (bid - 17408) * 256 + threadIdx.x; n4 = 524032;
    }
    if (i >= n4) return;
    const float4 val = src[i];
    __nv_bfloat16 h0 = __float2bfloat16_rn(val.x), h1 = __float2bfloat16_rn(val.y);
    __nv_bfloat16 h2 = __float2bfloat16_rn(val.z), h3 = __float2bfloat16_rn(val.w);
    __nv_bfloat16 l0 = __float2bfloat16_rn(val.x - __bfloat162float(h0));
    __nv_bfloat16 l1 = __float2bfloat16_rn(val.y - __bfloat162float(h1));
    __nv_bfloat16 l2 = __float2bfloat16_rn(val.z - __bfloat162float(h2));
    __nv_bfloat16 l3 = __float2bfloat16_rn(val.w - __bfloat162float(h3));
    uint2 H, L;
    H.x = (us16(h1) << 16) | us16(h0); H.y = (us16(h3) << 16) | us16(h2);
    L.x = (us16(l1) << 16) | us16(l0); L.y = (us16(l3) << 16) | us16(l2);
    dh[i] = H; dl[i] = L;
}

// ---------------------------------------------------------------------------
// Pure-bf16 GEMM core (bf16x3): Round-9 proven config.
// CTA 128x128, 8 warps (2x4), warp 64x32. Swizzled smem, 3-stage pipeline.
// ---------------------------------------------------------------------------
#define GTS 8192
#define GSTAGE (4 * GTS)
#define GSM_BYTES (3 * GSTAGE)

__device__ __forceinline__ void gemm_core_bf(
    const __nv_bfloat16* __restrict__ Ah, const __nv_bfloat16* __restrict__ Al,
    const __nv_bfloat16* __restrict__ Bh, const __nv_bfloat16* __restrict__ Bl,
    int m0, int n0, int M, char* smc, float acc[4][4][4])
{
    const uint32_t sb = smem_u32(smc);
    const int tid = threadIdx.x;
    const int lane = tid & 31;
    const int wid = tid >> 5;
    const int wm = wid >> 2, wn = wid & 3;

    const __nv_bfloat16* gsrc[8];
    uint32_t soff[8];
    #pragma unroll
    for (int j = 0; j < 8; j++) {
        const int f = tid + 256 * j;
        const int tile = f >> 9;
        const int g = f & 511;
        const int row = g >> 2;
        const int ch = g & 3;
        int r = ((tile < 2) ? m0 : n0) + row;
        if (tile < 2 && r > M - 1) r = M - 1;
        const __nv_bfloat16* base = (tile == 0) ? Ah : (tile == 1) ? Al : (tile == 2) ? Bh : Bl;
        gsrc[j] = base + (size_t)r * C_DIM + ch * 8;
        soff[j] = (uint32_t)(tile * GTS) + sw64(row, ch);
    }

    #pragma unroll
    for (int j = 0; j < 8; j++) cp_async16(sb + soff[j], gsrc[j], true);
    cp_commit();
    #pragma unroll
    for (int j = 0; j < 8; j++) cp_async16(sb + GSTAGE + soff[j], gsrc[j] + 32, true);
    cp_commit();

    int stage = 0;
    for (int kc = 0; kc < 32; kc++) {
        if (kc < 31) cp_wait<1>(); else cp_wait<0>();
        __syncthreads();
        if (kc + 2 < 32) {
            const int pst = (stage + 2 >= 3) ? stage - 1 : stage + 2;
            const uint32_t pb = sb + (uint32_t)pst * GSTAGE;
            const int kof = (kc + 2) * 32;
            #pragma unroll
            for (int j = 0; j < 8; j++)
                cp_async16(pb + soff[j], gsrc[j] + kof, true);
            cp_commit();
        }
        const uint32_t sab = sb + (uint32_t)stage * GSTAGE;
        #pragma unroll
        for (int ks = 0; ks < 2; ks++) {
            const int c0 = ks * 2;
            uint32_t bh[2][4], bl[2][4];
            #pragma unroll
            for (int p = 0; p < 2; p++) {
                const int brow = wn * 32 + p * 16 + (lane & 7) + ((lane >> 4) << 3);
                const int bch = c0 + ((lane >> 3) & 1);
                const uint32_t ba = sab + 2 * GTS + sw64(brow, bch);
                ldsm_x4(bh[p], ba);
                ldsm_x4(bl[p], ba + GTS);
            }
            #pragma unroll
            for (int mt = 0; mt < 4; mt++) {
                const int arow = wm * 64 + mt * 16 + (lane & 15);
                const int ach = c0 + (lane >> 4);
                const uint32_t aa = sab + sw64(arow, ach);
                uint32_t ah[4], al[4];
                ldsm_x4(ah, aa);
                ldsm_x4(al, aa + GTS);
                #pragma unroll
                for (int nt = 0; nt < 4; nt++) {
                    const uint32_t* bhp = &bh[nt >> 1][(nt & 1) * 2];
                    const uint32_t* blp = &bl[nt >> 1][(nt & 1) * 2];
                    mma_bf16(acc[mt][nt], ah, bhp);
                    mma_bf16(acc[mt][nt], ah, blp);
                    mma_bf16(acc[mt][nt], al, bhp);
                }
            }
        }
        stage = (stage + 1 >= 3) ? 0 : stage + 1;
    }
}

// ---------------------------------------------------------------------------
// Mega projection: q,k,v,p in one launch (896 CTAs, tile 128x128).
// ---------------------------------------------------------------------------
__global__ void __launch_bounds__(256, 2)
proj_mega(const float* __restrict__ bq, const float* __restrict__ bk,
          const float* __restrict__ bv, const float* __restrict__ pbu)
{
    extern __shared__ char smc[];
    const int id = blockIdx.x;
    int op, mi, ni;
    if (id < 768) { op = id >> 8; const int r = id & 255; mi = r >> 3; ni = r & 7; }
    else          { op = 3; const int r = id - 768; mi = r >> 3; ni = r & 7; }

    const int inoff = (op == 0) ? OIQ : (op == 1) ? OIK : (op == 2) ? OIV : OIP;
    const int woff  = op * 1048576;
    const int M = (op == 3) ? P_DIM : BT_DIM;
    const int m0 = mi * 128, n0 = ni * 128;

    float acc[4][4][4] = {};
    gemm_core_bf(g_inh + inoff, g_inl + inoff, g_wh + woff, g_wl + woff,
                 m0, n0, M, smc, acc);

    const int lane = threadIdx.x & 31, wid = threadIdx.x >> 5;
    const int g = lane >> 2, tg = lane & 3, wm = wid >> 2, wn = wid & 3;
    __nv_bfloat16* gh = (op == 0) ? g_quh : (op == 1) ? g_kh : (op == 2) ? g_vh : g_ph;
    __nv_bfloat16* gl = (op == 0) ? g_qul : (op == 1) ? g_kl : (op == 2) ? g_vl : g_pl;

    #pragma unroll
    for (int mt = 0; mt < 4; mt++) {
        const int r0 = m0 + wm * 64 + mt * 16 + g;
        const int r1 = r0 + 8;
        #pragma unroll
        for (int nt = 0; nt < 4; nt++) {
            const int col = n0 + wn * 32 + nt * 8 + 2 * tg;
            float b0 = 0.f, b1 = 0.f;
            if (op == 0)      { b0 = bq[col] + pbu[col]; b1 = bq[col + 1] + pbu[col + 1]; }
            else if (op == 1) { b0 = bk[col]; b1 = bk[col + 1]; }
            else if (op == 2) { b0 = bv[col]; b1 = bv[col + 1]; }
            float x0 = acc[mt][nt][0] + b0, x1 = acc[mt][nt][1] + b1;
            float x2 = acc[mt][nt][2] + b0, x3 = acc[mt][nt][3] + b1;
            if (op == 0) { x0 *= 0.125f; x1 *= 0.125f; x2 *= 0.125f; x3 *= 0.125f; }
            if (r0 < M) st_pair_split(gh, gl, (size_t)r0 * C_DIM + col, x0, x1);
            if (r1 < M) st_pair_split(gh, gl, (size_t)r1 * C_DIM + col, x2, x3);
        }
    }
}

// Output projection: A = attention out (bf16 hi/lo), writes fp32 d_out.
__global__ void __launch_bounds__(256, 2)
gemm_out(const float* __restrict__ bias, float* __restrict__ Cout)
{
    extern __shared__ char smc[];
    const int mi = blockIdx.x >> 3, ni = blockIdx.x & 7;
    const int m0 = mi * 128, n0 = ni * 128;
    float acc[4][4][4] = {};
    gemm_core_bf(g_xh, g_xl, g_wh + OWO, g_wl + OWO, m0, n0, BT_DIM, smc, acc);

    const int lane = threadIdx.x & 31, wid = threadIdx.x >> 5;
    const int g = lane >> 2, tg = lane & 3, wm = wid >> 2, wn = wid & 3;
    #pragma unroll
    for (int mt = 0; mt < 4; mt++) {
        const int r0 = m0 + wm * 64 + mt * 16 + g;
        #pragma unroll
        for (int nt = 0; nt < 4; nt++) {
            const int col = n0 + wn * 32 + nt * 8 + 2 * tg;
            const float b0 = bias[col], b1 = bias[col + 1];
            *(float2*)(Cout + (size_t)r0 * C_DIM + col) =
                make_float2(acc[mt][nt][0] + b0, acc[mt][nt][1] + b1);
            *(float2*)(Cout + (size_t)(r0 + 8) * C_DIM + col) =
                make_float2(acc[mt][nt][2] + b0, acc[mt][nt][3] + b1);
        }
    }
}

// ---------------------------------------------------------------------------
// Attention (R9 64-row base, barrier-reduced):
//  - AC + G MMA fused before one barrier (EV published, K/band reads done)
//  - scatter -> exp: warp-private BD rows, __syncwarp only
//  - V double-buffered: odd iterations reuse the dead QU smem region
//    (QU lives in registers after the one-time fragment load)
//  Per-iter barriers: 4 (was 6). Grid (16,64), 128 threads, 111 KB smem,
//  2 CTAs/SM. BD fp32 staging aliases P tiles ACROSS WARPS -> the barrier
//  between exp (BD reads) and P stores is mandatory.
// ---------------------------------------------------------------------------
#define ATP 72
#define OQUH 0
#define OQUL 9216
#define OKH  18432
#define OKL  27648
#define OVH  36864
#define OVL  46080
#define OBH  55296
#define OBL  73728
#define OPH  92160
#define OPL  101376
#define OEV  110592
#define ODL  111104
#define ATT_BYTES 111360

__global__ void __launch_bounds__(128)
attn_bf16(const float* __restrict__ pbu, const float* __restrict__ pbv)
{
    extern __shared__ char smc[];
    const uint32_t sb = smem_u32(smc);
    const int tid = threadIdx.x;
    const int wid = tid >> 5;
    const int lane = tid & 31;
    const int g = lane >> 2, tg = lane & 3;
    const int t0 = blockIdx.x * 64;
    const int b = (int)blockIdx.y >> 4;
    const int h = (int)blockIdx.y & 15;
    const int row0w = wid * 16;
    const int row0g = row0w + g;
    const int cbase = 48 - row0w;

    // Prologue: G1 = K0 + band0, G2 = QU, G3 = V0 (-> OVH buffer)
    {
        const int w0 = 960 - t0;
        #pragma unroll
        for (int jj = 0; jj < 8; jj++) {
            const int f = tid + 128 * jj;
            const int half = f >> 9, rem = f & 511, row = rem >> 3, ch = rem & 7;
            const __nv_bfloat16* src = half ? g_kl : g_kh;
            const uint32_t dst = sb + (half ? OKL : OKH);
            cp_async16(dst + (uint32_t)((row * ATP + ch * 8) * 2),
                       src + ((size_t)row * B_DIM + b) * C_DIM + h * 64 + ch * 8, true);
        }
        #pragma unroll
        for (int jj = 0; jj < 16; jj++) {
            const int f = tid + 128 * jj;
            const int half = f >> 10, rem = f & 1023, row = rem >> 3, ch = rem & 7;
            if (row < 127) {
                const int pr = w0 + row;
                const int slot = pr & 127;
                const __nv_bfloat16* src = half ? g_pl : g_ph;
                const uint32_t dst = sb + (half ? OBL : OBH);
                cp_async16(dst + (uint32_t)((slot * ATP + ch * 8) * 2),
                           src + (size_t)pr * C_DIM + h * 64 + ch * 8, true);
            }
        }
        cp_commit();
        #pragma unroll
        for (int jj = 0; jj < 8; jj++) {
            const int f = tid + 128 * jj;
            const int half = f >> 9, rem = f & 511, row = rem >> 3, ch = rem & 7;
            const __nv_bfloat16* src = half ? g_qul : g_quh;
            const uint32_t dst = sb + (half ? OQUL : OQUH);
            cp_async16(dst + (uint32_t)((row * ATP + ch * 8) * 2),
                       src + ((size_t)(t0 + row) * B_DIM + b) * C_DIM + h * 64 + ch * 8, true);
        }
        cp_commit();
        #pragma unroll
        for (int jj = 0; jj < 8; jj++) {
            const int f = tid + 128 * jj;
            const int half = f >> 9, rem = f & 511, row = rem >> 3, ch = rem & 7;
            const __nv_bfloat16* src = half ? g_vl : g_vh;
            const uint32_t dst = sb + (half ? OVL : OVH);
            cp_async16(dst + (uint32_t)((row * ATP + ch * 8) * 2),
                       src + ((size_t)row * B_DIM + b) * C_DIM + h * 64 + ch * 8, true);
        }
        cp_commit();
    }

    if (tid < 64)
        ((float*)(smc + ODL))[tid] = (pbv[h * 64 + tid] - pbu[h * 64 + tid]) * 0.125f;

    cp_wait<1>();      // K0, band0, QU arrived (V0 pending)
    __syncthreads();

    // Loop-invariant QU fragments (after this, QU smem region is dead
    // and serves as the odd-iteration V buffer)
    uint32_t quh[4][4], qul[4][4];
    #pragma unroll
    for (int k = 0; k < 4; k++) {
        const uint32_t aa = a_addr(sb + OQUH, row0w, k * 16, lane, ATP);
        ldsm_x4(quh[k], aa);
        ldsm_x4(qul[k], aa + (OQUL - OQUH));
    }

    float oacc[8][4];
    #pragma unroll
    for (int nt = 0; nt < 8; nt++)
        #pragma unroll
        for (int r = 0; r < 4; r++) oacc[nt][r] = 0.f;
    float lp0 = 0.f, lp1 = 0.f;

    for (int it = 0; it < 16; it++) {
        const int s0 = it * 64;
        const int off = (s0 - t0 + 960) & 127;
        const int s0n = (s0 + 64 < T_DIM) ? s0 + 64 : s0;
        const int wnx = s0n - t0 + 960;
        const uint32_t vcur = (it & 1) ? (uint32_t)OQUH : (uint32_t)OVH;  // hi; lo at +9216
        const uint32_t vnxt = (it & 1) ? (uint32_t)OVH : (uint32_t)OQUH;

        cp_wait<1>();      // K_i, band_i done (V_i pending)
        __syncthreads();   // sync1: stage data visible; prev PV done

        // e[c] = delta . band[c]
        if (tid < 127) {
            const int phys = (off + tid) & 127;
            const __nv_bfloat162* bh2 = (const __nv_bfloat162*)((__nv_bfloat16*)(smc + OBH) + phys * ATP);
            const __nv_bfloat162* bl2 = (const __nv_bfloat162*)((__nv_bfloat16*)(smc + OBL) + phys * ATP);
            const float2* dl2 = (const float2*)(smc + ODL);
            float s = 0.f;
            #pragma unroll
            for (int d2 = 0; d2 < 32; d2++) {
                const __nv_bfloat162 hh = bh2[d2], ll = bl2[d2];
                const float2 dv = dl2[d2];
                s = fmaf(__bfloat162float(hh.x) + __bfloat162float(ll.x), dv.x, s);
                s = fmaf(__bfloat162float(hh.y) + __bfloat162float(ll.y), dv.y, s);
            }
            ((float*)(smc + OEV))[tid] = s;
        }

        // Stage 1: AC = Qu @ K^T
        float sacc[8][4];
        #pragma unroll
        for (int nt = 0; nt < 8; nt++)
            #pragma unroll
            for (int r = 0; r < 4; r++) sacc[nt][r] = 0.f;
        #pragma unroll
        for (int k = 0; k < 4; k++) {
            #pragma unroll
            for (int p = 0; p < 4; p++) {
                const uint32_t ba = b_addr(sb + OKH, p * 16, k * 16, lane, ATP);
                uint32_t bh4[4], bl4[4];
                ldsm_x4(bh4, ba);
                ldsm_x4(bl4, ba + (OKL - OKH));
                mma_bf16(sacc[2 * p],     quh[k], bh4);     mma_bf16(sacc[2 * p],     quh[k], bl4);
                mma_bf16(sacc[2 * p],     qul[k], bh4);
                mma_bf16(sacc[2 * p + 1], quh[k], bh4 + 2); mma_bf16(sacc[2 * p + 1], quh[k], bl4 + 2);
                mma_bf16(sacc[2 * p + 1], qul[k], bh4 + 2);
            }
        }

        // Stage 2 (fused): windowed G = Qu @ band^T (5 p-tiles)
        float gacc[10][4];
        #pragma unroll
        for (int nt = 0; nt < 10; nt++)
            #pragma unroll
            for (int r = 0; r < 4; r++) gacc[nt][r] = 0.f;
        #pragma unroll
        for (int k = 0; k < 4; k++) {
            #pragma unroll
            for (int p = 0; p < 5; p++) {
                const int basep = (off + cbase + p * 16) & 127;
                const uint32_t ba = b_addr(sb + OBH, basep, k * 16, lane, ATP);
                uint32_t bh4[4], bl4[4];
                ldsm_x4(bh4, ba);
                ldsm_x4(bl4, ba + (OBL - OBH));
                mma_bf16(gacc[2 * p],     quh[k], bh4);     mma_bf16(gacc[2 * p],     quh[k], bl4);
                mma_bf16(gacc[2 * p],     qul[k], bh4);
                mma_bf16(gacc[2 * p + 1], quh[k], bh4 + 2); mma_bf16(gacc[2 * p + 1], quh[k], bl4 + 2);
                mma_bf16(gacc[2 * p + 1], qul[k], bh4 + 2);
            }
        }
        __syncthreads();   // sync2: EV visible; K + band reads done by ALL warps
                           // (iter 0: also QU fragments consumed before V1 overwrite)

        // prefetch K_{i+1} + band_{i+1} (one group)
        #pragma unroll
        for (int jj = 0; jj < 8; jj++) {
            const int f = tid + 128 * jj;
            const int half = f >> 9, rem = f & 511, row = rem >> 3, ch = rem & 7;
            const __nv_bfloat16* src = half ? g_kl : g_kh;
            const uint32_t dst = sb + (half ? OKL : OKH);
            cp_async16(dst + (uint32_t)((row * ATP + ch * 8) * 2),
                       src + ((size_t)(s0n + row) * B_DIM + b) * C_DIM + h * 64 + ch * 8, true);
        }
        #pragma unroll
        for (int jj = 0; jj < 8; jj++) {
            const int f = tid + 128 * jj;
            const int half = f >> 9, rem = f & 511, row = rem >> 3, ch = rem & 7;
            const int pr = wnx + 63 + row;
            const int slot = pr & 127;
            const __nv_bfloat16* src = half ? g_pl : g_ph;
            const uint32_t dst = sb + (half ? OBL : OBH);
            cp_async16(dst + (uint32_t)((slot * ATP + ch * 8) * 2),
                       src + (size_t)pr * C_DIM + h * 64 + ch * 8, true);
        }
        cp_commit();
        // prefetch V_{i+1} into the other buffer (one group)
        #pragma unroll
        for (int jj = 0; jj < 8; jj++) {
            const int f = tid + 128 * jj;
            const int half = f >> 9, rem = f & 511, row = rem >> 3, ch = rem & 7;
            const __nv_bfloat16* src = half ? g_vl : g_vh;
            const uint32_t dst = sb + vnxt + (half ? 9216u : 0u);
            cp_async16(dst + (uint32_t)((row * ATP + ch * 8) * 2),
                       src + ((size_t)(s0n + row) * B_DIM + b) * C_DIM + h * 64 + ch * 8, true);
        }
        cp_commit();

        // scatter bd into BD (warp-private rows)
        {
            float* BD = (float*)(smc + OPH);
            const float* EV = (const float*)(smc + OEV);
            #pragma unroll
            for (int nt = 0; nt < 10; nt++)
                #pragma unroll
                for (int r2 = 0; r2 < 2; r2++) {
                    const int t = row0g + 8 * r2;
                    #pragma unroll
                    for (int cc = 0; cc < 2; cc++) {
                        const int c = cbase + nt * 8 + 2 * tg + cc;
                        const int s = c - 63 + t;
                        if (s >= 0 && s < 64)
                            BD[t * 68 + s] = gacc[nt][r2 * 2 + cc] + EV[c];
                    }
                }
        }
        __syncwarp();      // BD rows are warp-private: warp-level ordering suffices

        // Stage 3: P = exp(ac + bd)
        const float* BD = (const float*)(smc + OPH);
        float pval[8][4];
        #pragma unroll
        for (int nt = 0; nt < 8; nt++)
            #pragma unroll
            for (int r2 = 0; r2 < 2; r2++) {
                const int t = row0g + 8 * r2;
                #pragma unroll
                for (int cc = 0; cc < 2; cc++) {
                    const int s = nt * 8 + 2 * tg + cc;
                    float v = sacc[nt][r2 * 2 + cc] + BD[t * 68 + s];
                    v = __expf(fminf(v, 60.f));
                    pval[nt][r2 * 2 + cc] = v;
                    if (r2 == 0) lp0 += v; else lp1 += v;
                }
            }
        __syncthreads();   // sync3 (MANDATORY): BD fp32 aliases P tiles ACROSS warps
        {
            __nv_bfloat16* Ph = (__nv_bfloat16*)(smc + OPH);
            __nv_bfloat16* Pl = (__nv_bfloat16*)(smc + OPL);
            #pragma unroll
            for (int nt = 0; nt < 8; nt++)
                #pragma unroll
                for (int r2 = 0; r2 < 2; r2++) {
                    const int t = row0g + 8 * r2;
                    const int s = nt * 8 + 2 * tg;
                    st_pair_split(Ph, Pl, (size_t)(t * ATP + s),
                                  pval[nt][r2 * 2], pval[nt][r2 * 2 + 1]);
                }
        }
        __syncwarp();      // P rows warp-private: order stores before own ldmatrix
        cp_wait<2>();      // V_i arrived (K/band_{i+1}, V_{i+1} still in flight)
        __syncthreads();   // sync4: V_i visible to all warps

        // Stage 4: O += P @ V  (P rows own-warp; V from current buffer)
        #pragma unroll
        for (int k = 0; k < 4; k++) {
            const uint32_t pa = a_addr(sb + OPH, row0w, k * 16, lane, ATP);
            uint32_t aph[4], apl[4];
            ldsm_x4(aph, pa);
            ldsm_x4(apl, pa + (OPL - OPH));
            #pragma unroll
            for (int p = 0; p < 4; p++) {
                const uint32_t va = a_addr(sb + vcur, k * 16, p * 16, lane, ATP);
                uint32_t vh4[4], vl4[4];
                ldsm_x4t(vh4, va);
                ldsm_x4t(vl4, va + 9216u);
                mma_bf16(oacc[2 * p],     aph, vh4);     mma_bf16(oacc[2 * p],     aph, vl4);
                mma_bf16(oacc[2 * p],     apl, vh4);
                mma_bf16(oacc[2 * p + 1], aph, vh4 + 2); mma_bf16(oacc[2 * p + 1], aph, vl4 + 2);
                mma_bf16(oacc[2 * p + 1], apl, vh4 + 2);
            }
        }
        // no barrier: V_{i+2} prefetch (next iter, after sync2) is the first
        // writer of this buffer, and sync1+sync2 of iter i+1 orders it.
    }
    cp_wait<0>();

    lp0 += __shfl_xor_sync(0xffffffffu, lp0, 1);
    lp0 += __shfl_xor_sync(0xffffffffu, lp0, 2);
    lp1 += __shfl_xor_sync(0xffffffffu, lp1, 1);
    lp1 += __shfl_xor_sync(0xffffffffu, lp1, 2);
    const float inv0 = 1.f / lp0;
    const float inv1 = 1.f / lp1;

    #pragma unroll
    for (int nt = 0; nt < 8; nt++) {
        const int col = h * 64 + nt * 8 + 2 * tg;
        const size_t o0 = ((size_t)(t0 + row0g) * B_DIM + b) * C_DIM + col;
        const size_t o1 = ((size_t)(t0 + row0g + 8) * B_DIM + b) * C_DIM + col;
        st_pair_split(g_xh, g_xl, o0, oacc[nt][0] * inv0, oacc[nt][1] * inv0);
        st_pair_split(g_xh, g_xl, o1, oacc[nt][2] * inv1, oacc[nt][3] * inv1);
    }
}

// ---------------------------------------------------------------------------
// Launch
// ---------------------------------------------------------------------------
extern "C" void kernel_launch(void* const* d_in, const int* in_sizes, int n_in,
                              void* d_out, int out_size)
{
    const float* query   = (const float*)d_in[0];
    const float* key     = (const float*)d_in[1];
    const float* value   = (const float*)d_in[2];
    const float* pos_emb = (const float*)d_in[3];
    const float* Wq      = (const float*)d_in[4];
    const float* bq      = (const float*)d_in[5];
    const float* Wk      = (const float*)d_in[6];
    const float* bk      = (const float*)d_in[7];
    const float* Wv      = (const float*)d_in[8];
    const float* bv      = (const float*)d_in[9];
    const float* Wp      = (const float*)d_in[10];
    const float* Wo      = (const float*)d_in[11];
    const float* bo      = (const float*)d_in[12];
    const float* pbu     = (const float*)d_in[13];
    const float* pbv     = (const float*)d_in[14];
    float* out = (float*)d_out;

    cudaFuncSetAttribute(proj_mega, cudaFuncAttributeMaxDynamicSharedMemorySize, GSM_BYTES);
    cudaFuncSetAttribute(gemm_out,  cudaFuncAttributeMaxDynamicSharedMemorySize, GSM_BYTES);
    cudaFuncSetAttribute(attn_bf16, cudaFuncAttributeMaxDynamicSharedMemorySize, ATT_BYTES);

    split_all<<<19455, 256>>>((const float4*)Wq, (const float4*)Wk, (const float4*)Wv,
                              (const float4*)Wp, (const float4*)Wo,
                              (const float4*)query, (const float4*)key,
                              (const float4*)value, (const float4*)pos_emb);

    proj_mega<<<896, 256, GSM_BYTES>>>(bq, bk, bv, pbu);
    attn_bf16<<<dim3(16, 64), 128, ATT_BYTES>>>(pbu, pbv);
    gemm_out<<<256, 256, GSM_BYTES>>>(bo, out);
}

// round 13
// speedup vs baseline: 1.2717x; 1.2717x over previous
#include <cuda_runtime.h>
#include <cuda_bf16.h>
#include <cuda_fp16.h>
#include <math_constants.h>
#include <cstdint>

// Problem constants
#define T_DIM 1024
#define B_DIM 4
#define C_DIM 1024
#define H_DIM 16
#define D_DIM 64
#define P_DIM 2047
#define BT_DIM (B_DIM * T_DIM)

// Scratch (device globals). Row order m = t*B + b ([T,B,C] natural).
// bf16 attention operands (written by proj epilogue, consumed by attn):
__device__ __nv_bfloat16 g_quh[BT_DIM * C_DIM];  // (q@Wq+bq+pbu)*0.125 hi
__device__ __nv_bfloat16 g_qul[BT_DIM * C_DIM];
__device__ __nv_bfloat16 g_kh[BT_DIM * C_DIM];
__device__ __nv_bfloat16 g_kl[BT_DIM * C_DIM];
__device__ __nv_bfloat16 g_vh[BT_DIM * C_DIM];
__device__ __nv_bfloat16 g_vl[BT_DIM * C_DIM];
__device__ __nv_bfloat16 g_ph[P_DIM * C_DIM];
__device__ __nv_bfloat16 g_pl[P_DIM * C_DIM];
// fp16 GEMM operands:
__device__ __half g_x16h[BT_DIM * C_DIM];        // attention out hi/lo (fp16)
__device__ __half g_x16l[BT_DIM * C_DIM];
#define OWQ 0
#define OWK 1048576
#define OWV 2097152
#define OWP 3145728
#define OWO 4194304
__device__ __half g_w16[5 * 1048576];            // weights, fp16 hi only
#define OIQ 0
#define OIK 4194304
#define OIV 8388608
#define OIP 12582912
__device__ __half g_i16h[14679040];              // inputs, fp16 hi
__device__ __half g_i16l[14679040];              // inputs, fp16 lo

// ---------------------------------------------------------------------------
// Helpers
// ---------------------------------------------------------------------------
__device__ __forceinline__ uint32_t smem_u32(const void* p) {
    uint32_t a;
    asm("{ .reg .u64 t; cvta.to.shared.u64 t, %1; cvt.u32.u64 %0, t; }" : "=r"(a) : "l"(p));
    return a;
}
__device__ __forceinline__ void cp_async16(uint32_t saddr, const void* gptr, bool pred) {
    const int sz = pred ? 16 : 0;
    asm volatile("cp.async.cg.shared.global [%0], [%1], 16, %2;"
                 :: "r"(saddr), "l"(gptr), "r"(sz));
}
__device__ __forceinline__ void cp_commit() { asm volatile("cp.async.commit_group;"); }
template <int N>
__device__ __forceinline__ void cp_wait() { asm volatile("cp.async.wait_group %0;" :: "n"(N)); }

__device__ __forceinline__ void ldsm_x4(uint32_t* r, uint32_t a) {
    asm volatile("ldmatrix.sync.aligned.m8n8.x4.shared.b16 {%0,%1,%2,%3}, [%4];"
                 : "=r"(r[0]), "=r"(r[1]), "=r"(r[2]), "=r"(r[3]) : "r"(a));
}
__device__ __forceinline__ void ldsm_x4t(uint32_t* r, uint32_t a) {
    asm volatile("ldmatrix.sync.aligned.m8n8.x4.trans.shared.b16 {%0,%1,%2,%3}, [%4];"
                 : "=r"(r[0]), "=r"(r[1]), "=r"(r[2]), "=r"(r[3]) : "r"(a));
}
__device__ __forceinline__ void mma_bf16(float* c, const uint32_t* a, const uint32_t* b) {
    asm volatile("mma.sync.aligned.m16n8k16.row.col.f32.bf16.bf16.f32 "
                 "{%0,%1,%2,%3}, {%4,%5,%6,%7}, {%8,%9}, {%0,%1,%2,%3};"
                 : "+f"(c[0]), "+f"(c[1]), "+f"(c[2]), "+f"(c[3])
                 : "r"(a[0]), "r"(a[1]), "r"(a[2]), "r"(a[3]), "r"(b[0]), "r"(b[1]));
}
__device__ __forceinline__ void mma_fp16(float* c, const uint32_t* a, const uint32_t* b) {
    asm volatile("mma.sync.aligned.m16n8k16.row.col.f32.f16.f16.f32 "
                 "{%0,%1,%2,%3}, {%4,%5,%6,%7}, {%8,%9}, {%0,%1,%2,%3};"
                 : "+f"(c[0]), "+f"(c[1]), "+f"(c[2]), "+f"(c[3])
                 : "r"(a[0]), "r"(a[1]), "r"(a[2]), "r"(a[3]), "r"(b[0]), "r"(b[1]));
}
__device__ __forceinline__ uint32_t us16(__nv_bfloat16 h) { return (uint32_t)__bfloat16_as_ushort(h); }
__device__ __forceinline__ uint32_t uh16(__half h) { return (uint32_t)__half_as_ushort(h); }

// Padded-pitch fragment addressing (attention kernel)
__device__ __forceinline__ uint32_t a_addr(uint32_t base, int row0, int k0, int lane, int pitch) {
    const int row = row0 + (lane & 15);
    const int col = k0 + ((lane >> 4) << 3);
    return base + (uint32_t)((row * pitch + col) * 2);
}
__device__ __forceinline__ uint32_t b_addr(uint32_t base, int n0, int k0, int lane, int pitch) {
    const int row = n0 + (lane & 7) + ((lane >> 4) << 3);
    const int col = k0 + (lane & 8);
    return base + (uint32_t)((row * pitch + col) * 2);
}

// Swizzled 64B-row tile addressing (GEMM core): rows x 32 halfwords, no padding.
__device__ __forceinline__ uint32_t sw64(int row, int chunk) {
    return (uint32_t)((row << 6) + (((chunk ^ (row >> 1)) & 3) << 4));
}

__device__ __forceinline__ void st_pair_split(__nv_bfloat16* gh, __nv_bfloat16* gl,
                                              size_t off, float x0, float x1) {
    __nv_bfloat16 h0 = __float2bfloat16_rn(x0), h1 = __float2bfloat16_rn(x1);
    __nv_bfloat16 l0 = __float2bfloat16_rn(x0 - __bfloat162float(h0));
    __nv_bfloat16 l1 = __float2bfloat16_rn(x1 - __bfloat162float(h1));
    *(__nv_bfloat162*)(gh + off) = __halves2bfloat162(h0, h1);
    *(__nv_bfloat162*)(gl + off) = __halves2bfloat162(l0, l1);
}
__device__ __forceinline__ void st_pair_split_h(__half* gh, __half* gl,
                                                size_t off, float x0, float x1) {
    __half h0 = __float2half_rn(x0), h1 = __float2half_rn(x1);
    __half l0 = __float2half_rn(x0 - __half2float(h0));
    __half l1 = __float2half_rn(x1 - __half2float(h1));
    *(__half2*)(gh + off) = __halves2half2(h0, h1);
    *(__half2*)(gl + off) = __halves2half2(l0, l1);
}

// ---------------------------------------------------------------------------
// Merged setup: weights -> fp16 hi only; inputs -> fp16 hi+lo. ONE launch.
// ---------------------------------------------------------------------------
__global__ void __launch_bounds__(256)
split_all(const float4* __restrict__ Wq, const float4* __restrict__ Wk,
          const float4* __restrict__ Wv, const float4* __restrict__ Wp,
          const float4* __restrict__ Wo,
          const float4* __restrict__ q, const float4* __restrict__ k,
          const float4* __restrict__ v, const float4* __restrict__ p)
{
    const int bid = blockIdx.x;
    if (bid < 5120) {
        const int w = bid >> 10;
        const float4* src = (w == 0) ? Wq : (w == 1) ? Wk : (w == 2) ? Wv : (w == 3) ? Wp : Wo;
        const int i = (bid & 1023) * 256 + threadIdx.x;
        if (i >= 262144) return;
        const float4 val = src[i];
        const uint32_t h0 = uh16(__float2half_rn(val.x)), h1 = uh16(__float2half_rn(val.y));
        const uint32_t h2 = uh16(__float2half_rn(val.z)), h3 = uh16(__float2half_rn(val.w));
        uint2 H; H.x = (h1 << 16) | h0; H.y = (h3 << 16) | h2;
        ((uint2*)(g_w16 + w * 1048576))[i] = H;
        return;
    }
    const float4* src;
    __half *dh, *dl;
    int i, n4;
    if (bid < 9216) {
        src = q; dh = g_i16h + OIQ; dl = g_i16l + OIQ;
        i = (bid - 5120) * 256 + threadIdx.x; n4 = 1048576;
    } else if (bid < 13312) {
        src = k; dh = g_i16h + OIK; dl = g_i16l + OIK;
        i = (bid - 9216) * 256 + threadIdx.x; n4 = 1048576;
    } else if (bid < 17408) {
        src = v; dh = g_i16h + OIV; dl = g_i16l + OIV;
        i = (bid - 13312) * 256 + threadIdx.x; n4 = 1048576;
    } else {
        src = p; dh = g_i16h + OIP; dl = g_i16l + OIP;
        i = (bid - 17408) * 256 + threadIdx.x; n4 = 524032;
    }
    if (i >= n4) return;
    const float4 val = src[i];
    __half h0 = __float2half_rn(val.x), h1 = __float2half_rn(val.y);
    __half h2 = __float2half_rn(val.z), h3 = __float2half_rn(val.w);
    __half l0 = __float2half_rn(val.x - __half2float(h0));
    __half l1 = __float2half_rn(val.y - __half2float(h1));
    __half l2 = __float2half_rn(val.z - __half2float(h2));
    __half l3 = __float2half_rn(val.w - __half2float(h3));
    uint2 H, L;
    H.x = (uh16(h1) << 16) | uh16(h0); H.y = (uh16(h3) << 16) | uh16(h2);
    L.x = (uh16(l1) << 16) | uh16(l0); L.y = (uh16(l3) << 16) | uh16(l2);
    ((uint2*)dh)[i] = H;
    ((uint2*)dl)[i] = L;
}

// ---------------------------------------------------------------------------
// fp16 x2 GEMM core: C = (Ah+Al) @ Bh^T. A exact (fp16 hi+lo), B fp16 hi.
// CTA 128x128, 8 warps (2x4), warp 64x32. Swizzled smem, 3-stage pipeline,
// one barrier per K-chunk, prefetch distance 2 chunks. 2 MMAs per (mt,nt,ks).
// Stage = Ah(8K) + Al(8K) + Bh(8K) = 24 KB; 3 stages = 72 KB -> 2 CTAs/SM.
// ---------------------------------------------------------------------------
#define FTS 8192
#define FSTG (3 * FTS)
#define FSM_BYTES (3 * FSTG)

__device__ __forceinline__ void gemm_core_f16(
    const __half* __restrict__ Ah, const __half* __restrict__ Al,
    const __half* __restrict__ Bh,
    int m0, int n0, int M, char* smc, float acc[4][4][4])
{
    const uint32_t sb = smem_u32(smc);
    const int tid = threadIdx.x;
    const int lane = tid & 31;
    const int wid = tid >> 5;
    const int wm = wid >> 2, wn = wid & 3;

    const __half* gsrc[6];
    uint32_t soff[6];
    #pragma unroll
    for (int j = 0; j < 6; j++) {
        const int f = tid + 256 * j;       // 0..1535
        const int tile = f >> 9;            // 0=Ah 1=Al 2=Bh
        const int idx = f & 511;
        const int row = idx >> 2;
        const int ch = idx & 3;
        int r = ((tile < 2) ? m0 : n0) + row;
        if (tile < 2 && r > M - 1) r = M - 1;
        const __half* base = (tile == 0) ? Ah : (tile == 1) ? Al : Bh;
        gsrc[j] = base + (size_t)r * C_DIM + ch * 8;
        soff[j] = (uint32_t)(tile * FTS) + sw64(row, ch);
    }

    #pragma unroll
    for (int j = 0; j < 6; j++) cp_async16(sb + soff[j], gsrc[j], true);
    cp_commit();
    #pragma unroll
    for (int j = 0; j < 6; j++) cp_async16(sb + FSTG + soff[j], gsrc[j] + 32, true);
    cp_commit();

    int stage = 0;
    for (int kc = 0; kc < 32; kc++) {
        if (kc < 31) cp_wait<1>(); else cp_wait<0>();
        __syncthreads();
        if (kc + 2 < 32) {
            const int pst = (stage + 2 >= 3) ? stage - 1 : stage + 2;
            const uint32_t pb = sb + (uint32_t)pst * FSTG;
            const int kof = (kc + 2) * 32;
            #pragma unroll
            for (int j = 0; j < 6; j++)
                cp_async16(pb + soff[j], gsrc[j] + kof, true);
            cp_commit();
        }
        const uint32_t sab = sb + (uint32_t)stage * FSTG;
        #pragma unroll
        for (int ks = 0; ks < 2; ks++) {
            const int c0 = ks * 2;
            uint32_t bh[2][4];
            #pragma unroll
            for (int p = 0; p < 2; p++) {
                const int brow = wn * 32 + p * 16 + (lane & 7) + ((lane >> 4) << 3);
                const int bch = c0 + ((lane >> 3) & 1);
                ldsm_x4(bh[p], sab + 2 * FTS + sw64(brow, bch));
            }
            #pragma unroll
            for (int mt = 0; mt < 4; mt++) {
                const int arow = wm * 64 + mt * 16 + (lane & 15);
                const int ach = c0 + (lane >> 4);
                const uint32_t aa = sab + sw64(arow, ach);
                uint32_t ah[4], al[4];
                ldsm_x4(ah, aa);
                ldsm_x4(al, aa + FTS);
                #pragma unroll
                for (int nt = 0; nt < 4; nt++) {
                    const uint32_t* bhp = &bh[nt >> 1][(nt & 1) * 2];
                    mma_fp16(acc[mt][nt], ah, bhp);
                    mma_fp16(acc[mt][nt], al, bhp);
                }
            }
        }
        stage = (stage + 1 >= 3) ? 0 : stage + 1;
    }
}

// ---------------------------------------------------------------------------
// Mega projection: q,k,v,p in one launch (896 CTAs, tile 128x128).
// fp16x2 core; epilogue writes bf16 hi/lo attention operands.
// ---------------------------------------------------------------------------
__global__ void __launch_bounds__(256, 2)
proj_mega(const float* __restrict__ bq, const float* __restrict__ bk,
          const float* __restrict__ bv, const float* __restrict__ pbu)
{
    extern __shared__ char smc[];
    const int id = blockIdx.x;
    int op, mi, ni;
    if (id < 768) { op = id >> 8; const int r = id & 255; mi = r >> 3; ni = r & 7; }
    else          { op = 3; const int r = id - 768; mi = r >> 3; ni = r & 7; }

    const int inoff = (op == 0) ? OIQ : (op == 1) ? OIK : (op == 2) ? OIV : OIP;
    const int woff  = op * 1048576;
    const int M = (op == 3) ? P_DIM : BT_DIM;
    const int m0 = mi * 128, n0 = ni * 128;

    float acc[4][4][4] = {};
    gemm_core_f16(g_i16h + inoff, g_i16l + inoff, g_w16 + woff, m0, n0, M, smc, acc);

    const int lane = threadIdx.x & 31, wid = threadIdx.x >> 5;
    const int g = lane >> 2, tg = lane & 3, wm = wid >> 2, wn = wid & 3;
    __nv_bfloat16* gh = (op == 0) ? g_quh : (op == 1) ? g_kh : (op == 2) ? g_vh : g_ph;
    __nv_bfloat16* gl = (op == 0) ? g_qul : (op == 1) ? g_kl : (op == 2) ? g_vl : g_pl;

    #pragma unroll
    for (int mt = 0; mt < 4; mt++) {
        const int r0 = m0 + wm * 64 + mt * 16 + g;
        const int r1 = r0 + 8;
        #pragma unroll
        for (int nt = 0; nt < 4; nt++) {
            const int col = n0 + wn * 32 + nt * 8 + 2 * tg;
            float b0 = 0.f, b1 = 0.f;
            if (op == 0)      { b0 = bq[col] + pbu[col]; b1 = bq[col + 1] + pbu[col + 1]; }
            else if (op == 1) { b0 = bk[col]; b1 = bk[col + 1]; }
            else if (op == 2) { b0 = bv[col]; b1 = bv[col + 1]; }
            float x0 = acc[mt][nt][0] + b0, x1 = acc[mt][nt][1] + b1;
            float x2 = acc[mt][nt][2] + b0, x3 = acc[mt][nt][3] + b1;
            if (op == 0) { x0 *= 0.125f; x1 *= 0.125f; x2 *= 0.125f; x3 *= 0.125f; }
            if (r0 < M) st_pair_split(gh, gl, (size_t)r0 * C_DIM + col, x0, x1);
            if (r1 < M) st_pair_split(gh, gl, (size_t)r1 * C_DIM + col, x2, x3);
        }
    }
}

// Output projection: A = attention out (fp16 hi/lo), writes fp32 d_out.
__global__ void __launch_bounds__(256, 2)
gemm_out(const float* __restrict__ bias, float* __restrict__ Cout)
{
    extern __shared__ char smc[];
    const int mi = blockIdx.x >> 3, ni = blockIdx.x & 7;
    const int m0 = mi * 128, n0 = ni * 128;
    float acc[4][4][4] = {};
    gemm_core_f16(g_x16h, g_x16l, g_w16 + OWO, m0, n0, BT_DIM, smc, acc);

    const int lane = threadIdx.x & 31, wid = threadIdx.x >> 5;
    const int g = lane >> 2, tg = lane & 3, wm = wid >> 2, wn = wid & 3;
    #pragma unroll
    for (int mt = 0; mt < 4; mt++) {
        const int r0 = m0 + wm * 64 + mt * 16 + g;
        #pragma unroll
        for (int nt = 0; nt < 4; nt++) {
            const int col = n0 + wn * 32 + nt * 8 + 2 * tg;
            const float b0 = bias[col], b1 = bias[col + 1];
            *(float2*)(Cout + (size_t)r0 * C_DIM + col) =
                make_float2(acc[mt][nt][0] + b0, acc[mt][nt][1] + b1);
            *(float2*)(Cout + (size_t)(r0 + 8) * C_DIM + col) =
                make_float2(acc[mt][nt][2] + b0, acc[mt][nt][3] + b1);
        }
    }
}

// ---------------------------------------------------------------------------
// Attention: Round-9 proven structure (bf16x3), unchanged except the final
// store writes fp16 hi/lo for the fp16x2 output GEMM.
// NOTE: BD fp32 staging aliases the P bf16 tiles ACROSS WARPS — the barrier
// between exp (BD reads) and P stores is mandatory.
// ---------------------------------------------------------------------------
#define ATP 72
#define OQUH 0
#define OQUL 9216
#define OKH  18432
#define OKL  27648
#define OVH  36864
#define OVL  46080
#define OBH  55296
#define OBL  73728
#define OPH  92160
#define OPL  101376
#define OEV  110592
#define ODL  111104
#define ATT_BYTES 111360

__global__ void __launch_bounds__(128)
attn_bf16(const float* __restrict__ pbu, const float* __restrict__ pbv)
{
    extern __shared__ char smc[];
    const uint32_t sb = smem_u32(smc);
    const int tid = threadIdx.x;
    const int wid = tid >> 5;
    const int lane = tid & 31;
    const int g = lane >> 2, tg = lane & 3;
    const int t0 = blockIdx.x * 64;
    const int b = (int)blockIdx.y >> 4;
    const int h = (int)blockIdx.y & 15;
    const int row0w = wid * 16;
    const int row0g = row0w + g;
    const int cbase = 48 - row0w;

    {
        const int w0 = 960 - t0;
        #pragma unroll
        for (int jj = 0; jj < 8; jj++) {
            const int f = tid + 128 * jj;
            const int half = f >> 9, rem = f & 511, row = rem >> 3, ch = rem & 7;
            const __nv_bfloat16* src = half ? g_kl : g_kh;
            const uint32_t dst = sb + (half ? OKL : OKH);
            cp_async16(dst + (uint32_t)((row * ATP + ch * 8) * 2),
                       src + ((size_t)row * B_DIM + b) * C_DIM + h * 64 + ch * 8, true);
        }
        #pragma unroll
        for (int jj = 0; jj < 16; jj++) {
            const int f = tid + 128 * jj;
            const int half = f >> 10, rem = f & 1023, row = rem >> 3, ch = rem & 7;
            if (row < 127) {
                const int pr = w0 + row;
                const int slot = pr & 127;
                const __nv_bfloat16* src = half ? g_pl : g_ph;
                const uint32_t dst = sb + (half ? OBL : OBH);
                cp_async16(dst + (uint32_t)((slot * ATP + ch * 8) * 2),
                           src + (size_t)pr * C_DIM + h * 64 + ch * 8, true);
            }
        }
        cp_commit();
        #pragma unroll
        for (int jj = 0; jj < 8; jj++) {
            const int f = tid + 128 * jj;
            const int half = f >> 9, rem = f & 511, row = rem >> 3, ch = rem & 7;
            const __nv_bfloat16* src = half ? g_qul : g_quh;
            const uint32_t dst = sb + (half ? OQUL : OQUH);
            cp_async16(dst + (uint32_t)((row * ATP + ch * 8) * 2),
                       src + ((size_t)(t0 + row) * B_DIM + b) * C_DIM + h * 64 + ch * 8, true);
        }
        cp_commit();
        #pragma unroll
        for (int jj = 0; jj < 8; jj++) {
            const int f = tid + 128 * jj;
            const int half = f >> 9, rem = f & 511, row = rem >> 3, ch = rem & 7;
            const __nv_bfloat16* src = half ? g_vl : g_vh;
            const uint32_t dst = sb + (half ? OVL : OVH);
            cp_async16(dst + (uint32_t)((row * ATP + ch * 8) * 2),
                       src + ((size_t)row * B_DIM + b) * C_DIM + h * 64 + ch * 8, true);
        }
        cp_commit();
    }

    if (tid < 64)
        ((float*)(smc + ODL))[tid] = (pbv[h * 64 + tid] - pbu[h * 64 + tid]) * 0.125f;

    cp_wait<1>();
    __syncthreads();

    uint32_t quh[4][4], qul[4][4];
    #pragma unroll
    for (int k = 0; k < 4; k++) {
        const uint32_t aa = a_addr(sb + OQUH, row0w, k * 16, lane, ATP);
        ldsm_x4(quh[k], aa);
        ldsm_x4(qul[k], aa + (OQUL - OQUH));
    }

    float oacc[8][4];
    #pragma unroll
    for (int nt = 0; nt < 8; nt++)
        #pragma unroll
        for (int r = 0; r < 4; r++) oacc[nt][r] = 0.f;
    float lp0 = 0.f, lp1 = 0.f;

    for (int it = 0; it < 16; it++) {
        const int s0 = it * 64;
        const int off = (s0 - t0 + 960) & 127;
        const int s0n = (s0 + 64 < T_DIM) ? s0 + 64 : s0;
        const int wnx = s0n - t0 + 960;

        cp_wait<1>();
        __syncthreads();

        if (tid < 127) {
            const int phys = (off + tid) & 127;
            const __nv_bfloat162* bh2 = (const __nv_bfloat162*)((__nv_bfloat16*)(smc + OBH) + phys * ATP);
            const __nv_bfloat162* bl2 = (const __nv_bfloat162*)((__nv_bfloat16*)(smc + OBL) + phys * ATP);
            const float2* dl2 = (const float2*)(smc + ODL);
            float s = 0.f;
            #pragma unroll
            for (int d2 = 0; d2 < 32; d2++) {
                const __nv_bfloat162 hh = bh2[d2], ll = bl2[d2];
                const float2 dv = dl2[d2];
                s = fmaf(__bfloat162float(hh.x) + __bfloat162float(ll.x), dv.x, s);
                s = fmaf(__bfloat162float(hh.y) + __bfloat162float(ll.y), dv.y, s);
            }
            ((float*)(smc + OEV))[tid] = s;
        }

        float sacc[8][4];
        #pragma unroll
        for (int nt = 0; nt < 8; nt++)
            #pragma unroll
            for (int r = 0; r < 4; r++) sacc[nt][r] = 0.f;
        #pragma unroll
        for (int k = 0; k < 4; k++) {
            #pragma unroll
            for (int p = 0; p < 4; p++) {
                const uint32_t ba = b_addr(sb + OKH, p * 16, k * 16, lane, ATP);
                uint32_t bh4[4], bl4[4];
                ldsm_x4(bh4, ba);
                ldsm_x4(bl4, ba + (OKL - OKH));
                mma_bf16(sacc[2 * p],     quh[k], bh4);     mma_bf16(sacc[2 * p],     quh[k], bl4);
                mma_bf16(sacc[2 * p],     qul[k], bh4);
                mma_bf16(sacc[2 * p + 1], quh[k], bh4 + 2); mma_bf16(sacc[2 * p + 1], quh[k], bl4 + 2);
                mma_bf16(sacc[2 * p + 1], qul[k], bh4 + 2);
            }
        }
        __syncthreads();

        #pragma unroll
        for (int jj = 0; jj < 8; jj++) {
            const int f = tid + 128 * jj;
            const int half = f >> 9, rem = f & 511, row = rem >> 3, ch = rem & 7;
            const __nv_bfloat16* src = half ? g_kl : g_kh;
            const uint32_t dst = sb + (half ? OKL : OKH);
            cp_async16(dst + (uint32_t)((row * ATP + ch * 8) * 2),
                       src + ((size_t)(s0n + row) * B_DIM + b) * C_DIM + h * 64 + ch * 8, true);
        }
        cp_commit();

        float gacc[10][4];
        #pragma unroll
        for (int nt = 0; nt < 10; nt++)
            #pragma unroll
            for (int r = 0; r < 4; r++) gacc[nt][r] = 0.f;
        #pragma unroll
        for (int k = 0; k < 4; k++) {
            #pragma unroll
            for (int p = 0; p < 5; p++) {
                const int basep = (off + cbase + p * 16) & 127;
                const uint32_t ba = b_addr(sb + OBH, basep, k * 16, lane, ATP);
                uint32_t bh4[4], bl4[4];
                ldsm_x4(bh4, ba);
                ldsm_x4(bl4, ba + (OBL - OBH));
                mma_bf16(gacc[2 * p],     quh[k], bh4);     mma_bf16(gacc[2 * p],     quh[k], bl4);
                mma_bf16(gacc[2 * p],     qul[k], bh4);
                mma_bf16(gacc[2 * p + 1], quh[k], bh4 + 2); mma_bf16(gacc[2 * p + 1], quh[k], bl4 + 2);
                mma_bf16(gacc[2 * p + 1], qul[k], bh4 + 2);
            }
        }
        {
            float* BD = (float*)(smc + OPH);
            const float* EV = (const float*)(smc + OEV);
            #pragma unroll
            for (int nt = 0; nt < 10; nt++)
                #pragma unroll
                for (int r2 = 0; r2 < 2; r2++) {
                    const int t = row0g + 8 * r2;
                    #pragma unroll
                    for (int cc = 0; cc < 2; cc++) {
                        const int c = cbase + nt * 8 + 2 * tg + cc;
                        const int s = c - 63 + t;
                        if (s >= 0 && s < 64)
                            BD[t * 68 + s] = gacc[nt][r2 * 2 + cc] + EV[c];
                    }
                }
        }
        __syncthreads();

        #pragma unroll
        for (int jj = 0; jj < 8; jj++) {
            const int f = tid + 128 * jj;
            const int half = f >> 9, rem = f & 511, row = rem >> 3, ch = rem & 7;
            const int pr = wnx + 63 + row;
            const int slot = pr & 127;
            const __nv_bfloat16* src = half ? g_pl : g_ph;
            const uint32_t dst = sb + (half ? OBL : OBH);
            cp_async16(dst + (uint32_t)((slot * ATP + ch * 8) * 2),
                       src + (size_t)pr * C_DIM + h * 64 + ch * 8, true);
        }
        cp_commit();

        const float* BD = (const float*)(smc + OPH);
        float pval[8][4];
        #pragma unroll
        for (int nt = 0; nt < 8; nt++)
            #pragma unroll
            for (int r2 = 0; r2 < 2; r2++) {
                const int t = row0g + 8 * r2;
                #pragma unroll
                for (int cc = 0; cc < 2; cc++) {
                    const int s = nt * 8 + 2 * tg + cc;
                    float v = sacc[nt][r2 * 2 + cc] + BD[t * 68 + s];
                    v = __expf(fminf(v, 60.f));
                    pval[nt][r2 * 2 + cc] = v;
                    if (r2 == 0) lp0 += v; else lp1 += v;
                }
            }
        __syncthreads();   // MANDATORY: BD aliases P tiles across warps
        {
            __nv_bfloat16* Ph = (__nv_bfloat16*)(smc + OPH);
            __nv_bfloat16* Pl = (__nv_bfloat16*)(smc + OPL);
            #pragma unroll
            for (int nt = 0; nt < 8; nt++)
                #pragma unroll
                for (int r2 = 0; r2 < 2; r2++) {
                    const int t = row0g + 8 * r2;
                    const int s = nt * 8 + 2 * tg;
                    st_pair_split(Ph, Pl, (size_t)(t * ATP + s),
                                  pval[nt][r2 * 2], pval[nt][r2 * 2 + 1]);
                }
        }
        cp_wait<2>();
        __syncthreads();

        #pragma unroll
        for (int k = 0; k < 4; k++) {
            const uint32_t pa = a_addr(sb + OPH, row0w, k * 16, lane, ATP);
            uint32_t aph[4], apl[4];
            ldsm_x4(aph, pa);
            ldsm_x4(apl, pa + (OPL - OPH));
            #pragma unroll
            for (int p = 0; p < 4; p++) {
                const uint32_t va = a_addr(sb + OVH, k * 16, p * 16, lane, ATP);
                uint32_t vh4[4], vl4[4];
                ldsm_x4t(vh4, va);
                ldsm_x4t(vl4, va + (OVL - OVH));
                mma_bf16(oacc[2 * p],     aph, vh4);     mma_bf16(oacc[2 * p],     aph, vl4);
                mma_bf16(oacc[2 * p],     apl, vh4);
                mma_bf16(oacc[2 * p + 1], aph, vh4 + 2); mma_bf16(oacc[2 * p + 1], aph, vl4 + 2);
                mma_bf16(oacc[2 * p + 1], apl, vh4 + 2);
            }
        }
        __syncthreads();

        #pragma unroll
        for (int jj = 0; jj < 8; jj++) {
            const int f = tid + 128 * jj;
            const int half = f >> 9, rem = f & 511, row = rem >> 3, ch = rem & 7;
            const __nv_bfloat16* src = half ? g_vl : g_vh;
            const uint32_t dst = sb + (half ? OVL : OVH);
            cp_async16(dst + (uint32_t)((row * ATP + ch * 8) * 2),
                       src + ((size_t)(s0n + row) * B_DIM + b) * C_DIM + h * 64 + ch * 8, true);
        }
        cp_commit();
    }
    cp_wait<0>();

    lp0 += __shfl_xor_sync(0xffffffffu, lp0, 1);
    lp0 += __shfl_xor_sync(0xffffffffu, lp0, 2);
    lp1 += __shfl_xor_sync(0xffffffffu, lp1, 1);
    lp1 += __shfl_xor_sync(0xffffffffu, lp1, 2);
    const float inv0 = 1.f / lp0;
    const float inv1 = 1.f / lp1;

    #pragma unroll
    for (int nt = 0; nt < 8; nt++) {
        const int col = h * 64 + nt * 8 + 2 * tg;
        const size_t o0 = ((size_t)(t0 + row0g) * B_DIM + b) * C_DIM + col;
        const size_t o1 = ((size_t)(t0 + row0g + 8) * B_DIM + b) * C_DIM + col;
        st_pair_split_h(g_x16h, g_x16l, o0, oacc[nt][0] * inv0, oacc[nt][1] * inv0);
        st_pair_split_h(g_x16h, g_x16l, o1, oacc[nt][2] * inv1, oacc[nt][3] * inv1);
    }
}

// ---------------------------------------------------------------------------
// Launch
// ---------------------------------------------------------------------------
extern "C" void kernel_launch(void* const* d_in, const int* in_sizes, int n_in,
                              void* d_out, int out_size)
{
    const float* query   = (const float*)d_in[0];
    const float* key     = (const float*)d_in[1];
    const float* value   = (const float*)d_in[2];
    const float* pos_emb = (const float*)d_in[3];
    const float* Wq      = (const float*)d_in[4];
    const float* bq      = (const float*)d_in[5];
    const float* Wk      = (const float*)d_in[6];
    const float* bk      = (const float*)d_in[7];
    const float* Wv      = (const float*)d_in[8];
    const float* bv      = (const float*)d_in[9];
    const float* Wp      = (const float*)d_in[10];
    const float* Wo      = (const float*)d_in[11];
    const float* bo      = (const float*)d_in[12];
    const float* pbu     = (const float*)d_in[13];
    const float* pbv     = (const float*)d_in[14];
    float* out = (float*)d_out;

    cudaFuncSetAttribute(proj_mega, cudaFuncAttributeMaxDynamicSharedMemorySize, FSM_BYTES);
    cudaFuncSetAttribute(gemm_out,  cudaFuncAttributeMaxDynamicSharedMemorySize, FSM_BYTES);
    cudaFuncSetAttribute(attn_bf16, cudaFuncAttributeMaxDynamicSharedMemorySize, ATT_BYTES);

    split_all<<<19455, 256>>>((const float4*)Wq, (const float4*)Wk, (const float4*)Wv,
                              (const float4*)Wp, (const float4*)Wo,
                              (const float4*)query, (const float4*)key,
                              (const float4*)value, (const float4*)pos_emb);

    proj_mega<<<896, 256, FSM_BYTES>>>(bq, bk, bv, pbu);
    attn_bf16<<<dim3(16, 64), 128, ATT_BYTES>>>(pbu, pbv);
    gemm_out<<<256, 256, FSM_BYTES>>>(bo, out);
}

// round 14
// speedup vs baseline: 1.5445x; 1.2145x over previous
#include <cuda_runtime.h>
#include <cuda_bf16.h>
#include <cuda_fp16.h>
#include <math_constants.h>
#include <cstdint>

// Problem constants
#define T_DIM 1024
#define B_DIM 4
#define C_DIM 1024
#define H_DIM 16
#define D_DIM 64
#define P_DIM 2047
#define BT_DIM (B_DIM * T_DIM)

// Scratch (device globals). Row order m = t*B + b ([T,B,C] natural).
// fp16 attention operands (written by proj epilogue, consumed by attn):
__device__ __half g_qu16h[BT_DIM * C_DIM];   // (q@Wq+bq+pbu)*0.125 hi
__device__ __half g_qu16l[BT_DIM * C_DIM];   // lo
__device__ __half g_k16[BT_DIM * C_DIM];     // hi only
__device__ __half g_v16[BT_DIM * C_DIM];     // hi only
__device__ __half g_p16[P_DIM * C_DIM];      // hi only
// fp16 GEMM operands:
__device__ __half g_x16h[BT_DIM * C_DIM];    // attention out hi/lo (fp16)
__device__ __half g_x16l[BT_DIM * C_DIM];
#define OWQ 0
#define OWK 1048576
#define OWV 2097152
#define OWP 3145728
#define OWO 4194304
__device__ __half g_w16[5 * 1048576];        // weights, fp16 hi only
#define OIQ 0
#define OIK 4194304
#define OIV 8388608
#define OIP 12582912
__device__ __half g_i16h[14679040];          // inputs, fp16 hi
__device__ __half g_i16l[14679040];          // inputs, fp16 lo

// ---------------------------------------------------------------------------
// Helpers
// ---------------------------------------------------------------------------
__device__ __forceinline__ uint32_t smem_u32(const void* p) {
    uint32_t a;
    asm("{ .reg .u64 t; cvta.to.shared.u64 t, %1; cvt.u32.u64 %0, t; }" : "=r"(a) : "l"(p));
    return a;
}
__device__ __forceinline__ void cp_async16(uint32_t saddr, const void* gptr, bool pred) {
    const int sz = pred ? 16 : 0;
    asm volatile("cp.async.cg.shared.global [%0], [%1], 16, %2;"
                 :: "r"(saddr), "l"(gptr), "r"(sz));
}
__device__ __forceinline__ void cp_commit() { asm volatile("cp.async.commit_group;"); }
template <int N>
__device__ __forceinline__ void cp_wait() { asm volatile("cp.async.wait_group %0;" :: "n"(N)); }

__device__ __forceinline__ void ldsm_x4(uint32_t* r, uint32_t a) {
    asm volatile("ldmatrix.sync.aligned.m8n8.x4.shared.b16 {%0,%1,%2,%3}, [%4];"
                 : "=r"(r[0]), "=r"(r[1]), "=r"(r[2]), "=r"(r[3]) : "r"(a));
}
__device__ __forceinline__ void ldsm_x4t(uint32_t* r, uint32_t a) {
    asm volatile("ldmatrix.sync.aligned.m8n8.x4.trans.shared.b16 {%0,%1,%2,%3}, [%4];"
                 : "=r"(r[0]), "=r"(r[1]), "=r"(r[2]), "=r"(r[3]) : "r"(a));
}
__device__ __forceinline__ void mma_fp16(float* c, const uint32_t* a, const uint32_t* b) {
    asm volatile("mma.sync.aligned.m16n8k16.row.col.f32.f16.f16.f32 "
                 "{%0,%1,%2,%3}, {%4,%5,%6,%7}, {%8,%9}, {%0,%1,%2,%3};"
                 : "+f"(c[0]), "+f"(c[1]), "+f"(c[2]), "+f"(c[3])
                 : "r"(a[0]), "r"(a[1]), "r"(a[2]), "r"(a[3]), "r"(b[0]), "r"(b[1]));
}
__device__ __forceinline__ uint32_t uh16(__half h) { return (uint32_t)__half_as_ushort(h); }

// Padded-pitch fragment addressing (attention kernel)
__device__ __forceinline__ uint32_t a_addr(uint32_t base, int row0, int k0, int lane, int pitch) {
    const int row = row0 + (lane & 15);
    const int col = k0 + ((lane >> 4) << 3);
    return base + (uint32_t)((row * pitch + col) * 2);
}
__device__ __forceinline__ uint32_t b_addr(uint32_t base, int n0, int k0, int lane, int pitch) {
    const int row = n0 + (lane & 7) + ((lane >> 4) << 3);
    const int col = k0 + (lane & 8);
    return base + (uint32_t)((row * pitch + col) * 2);
}

// Swizzled 64B-row tile addressing (GEMM core): rows x 32 halfwords, no padding.
__device__ __forceinline__ uint32_t sw64(int row, int chunk) {
    return (uint32_t)((row << 6) + (((chunk ^ (row >> 1)) & 3) << 4));
}

__device__ __forceinline__ void st_pair_split_h(__half* gh, __half* gl,
                                                size_t off, float x0, float x1) {
    __half h0 = __float2half_rn(x0), h1 = __float2half_rn(x1);
    __half l0 = __float2half_rn(x0 - __half2float(h0));
    __half l1 = __float2half_rn(x1 - __half2float(h1));
    *(__half2*)(gh + off) = __halves2half2(h0, h1);
    *(__half2*)(gl + off) = __halves2half2(l0, l1);
}

// ---------------------------------------------------------------------------
// Merged setup: weights -> fp16 hi only; inputs -> fp16 hi+lo. ONE launch.
// ---------------------------------------------------------------------------
__global__ void __launch_bounds__(256)
split_all(const float4* __restrict__ Wq, const float4* __restrict__ Wk,
          const float4* __restrict__ Wv, const float4* __restrict__ Wp,
          const float4* __restrict__ Wo,
          const float4* __restrict__ q, const float4* __restrict__ k,
          const float4* __restrict__ v, const float4* __restrict__ p)
{
    const int bid = blockIdx.x;
    if (bid < 5120) {
        const int w = bid >> 10;
        const float4* src = (w == 0) ? Wq : (w == 1) ? Wk : (w == 2) ? Wv : (w == 3) ? Wp : Wo;
        const int i = (bid & 1023) * 256 + threadIdx.x;
        if (i >= 262144) return;
        const float4 val = src[i];
        const uint32_t h0 = uh16(__float2half_rn(val.x)), h1 = uh16(__float2half_rn(val.y));
        const uint32_t h2 = uh16(__float2half_rn(val.z)), h3 = uh16(__float2half_rn(val.w));
        uint2 H; H.x = (h1 << 16) | h0; H.y = (h3 << 16) | h2;
        ((uint2*)(g_w16 + w * 1048576))[i] = H;
        return;
    }
    const float4* src;
    __half *dh, *dl;
    int i, n4;
    if (bid < 9216) {
        src = q; dh = g_i16h + OIQ; dl = g_i16l + OIQ;
        i = (bid - 5120) * 256 + threadIdx.x; n4 = 1048576;
    } else if (bid < 13312) {
        src = k; dh = g_i16h + OIK; dl = g_i16l + OIK;
        i = (bid - 9216) * 256 + threadIdx.x; n4 = 1048576;
    } else if (bid < 17408) {
        src = v; dh = g_i16h + OIV; dl = g_i16l + OIV;
        i = (bid - 13312) * 256 + threadIdx.x; n4 = 1048576;
    } else {
        src = p; dh = g_i16h + OIP; dl = g_i16l + OIP;
        i = (bid - 17408) * 256 + threadIdx.x; n4 = 524032;
    }
    if (i >= n4) return;
    const float4 val = src[i];
    __half h0 = __float2half_rn(val.x), h1 = __float2half_rn(val.y);
    __half h2 = __float2half_rn(val.z), h3 = __float2half_rn(val.w);
    __half l0 = __float2half_rn(val.x - __half2float(h0));
    __half l1 = __float2half_rn(val.y - __half2float(h1));
    __half l2 = __float2half_rn(val.z - __half2float(h2));
    __half l3 = __float2half_rn(val.w - __half2float(h3));
    uint2 H, L;
    H.x = (uh16(h1) << 16) | uh16(h0); H.y = (uh16(h3) << 16) | uh16(h2);
    L.x = (uh16(l1) << 16) | uh16(l0); L.y = (uh16(l3) << 16) | uh16(l2);
    ((uint2*)dh)[i] = H;
    ((uint2*)dl)[i] = L;
}

// ---------------------------------------------------------------------------
// fp16 x2 GEMM core: C = (Ah+Al) @ Bh^T. (R13 proven, unchanged.)
// ---------------------------------------------------------------------------
#define FTS 8192
#define FSTG (3 * FTS)
#define FSM_BYTES (3 * FSTG)

__device__ __forceinline__ void gemm_core_f16(
    const __half* __restrict__ Ah, const __half* __restrict__ Al,
    const __half* __restrict__ Bh,
    int m0, int n0, int M, char* smc, float acc[4][4][4])
{
    const uint32_t sb = smem_u32(smc);
    const int tid = threadIdx.x;
    const int lane = tid & 31;
    const int wid = tid >> 5;
    const int wm = wid >> 2, wn = wid & 3;

    const __half* gsrc[6];
    uint32_t soff[6];
    #pragma unroll
    for (int j = 0; j < 6; j++) {
        const int f = tid + 256 * j;
        const int tile = f >> 9;
        const int idx = f & 511;
        const int row = idx >> 2;
        const int ch = idx & 3;
        int r = ((tile < 2) ? m0 : n0) + row;
        if (tile < 2 && r > M - 1) r = M - 1;
        const __half* base = (tile == 0) ? Ah : (tile == 1) ? Al : Bh;
        gsrc[j] = base + (size_t)r * C_DIM + ch * 8;
        soff[j] = (uint32_t)(tile * FTS) + sw64(row, ch);
    }

    #pragma unroll
    for (int j = 0; j < 6; j++) cp_async16(sb + soff[j], gsrc[j], true);
    cp_commit();
    #pragma unroll
    for (int j = 0; j < 6; j++) cp_async16(sb + FSTG + soff[j], gsrc[j] + 32, true);
    cp_commit();

    int stage = 0;
    for (int kc = 0; kc < 32; kc++) {
        if (kc < 31) cp_wait<1>(); else cp_wait<0>();
        __syncthreads();
        if (kc + 2 < 32) {
            const int pst = (stage + 2 >= 3) ? stage - 1 : stage + 2;
            const uint32_t pb = sb + (uint32_t)pst * FSTG;
            const int kof = (kc + 2) * 32;
            #pragma unroll
            for (int j = 0; j < 6; j++)
                cp_async16(pb + soff[j], gsrc[j] + kof, true);
            cp_commit();
        }
        const uint32_t sab = sb + (uint32_t)stage * FSTG;
        #pragma unroll
        for (int ks = 0; ks < 2; ks++) {
            const int c0 = ks * 2;
            uint32_t bh[2][4];
            #pragma unroll
            for (int p = 0; p < 2; p++) {
                const int brow = wn * 32 + p * 16 + (lane & 7) + ((lane >> 4) << 3);
                const int bch = c0 + ((lane >> 3) & 1);
                ldsm_x4(bh[p], sab + 2 * FTS + sw64(brow, bch));
            }
            #pragma unroll
            for (int mt = 0; mt < 4; mt++) {
                const int arow = wm * 64 + mt * 16 + (lane & 15);
                const int ach = c0 + (lane >> 4);
                const uint32_t aa = sab + sw64(arow, ach);
                uint32_t ah[4], al[4];
                ldsm_x4(ah, aa);
                ldsm_x4(al, aa + FTS);
                #pragma unroll
                for (int nt = 0; nt < 4; nt++) {
                    const uint32_t* bhp = &bh[nt >> 1][(nt & 1) * 2];
                    mma_fp16(acc[mt][nt], ah, bhp);
                    mma_fp16(acc[mt][nt], al, bhp);
                }
            }
        }
        stage = (stage + 1 >= 3) ? 0 : stage + 1;
    }
}

// ---------------------------------------------------------------------------
// Mega projection: q,k,v,p in one launch (896 CTAs, tile 128x128).
// Epilogue writes fp16 attention operands (qu hi/lo; k,v,p hi only).
// ---------------------------------------------------------------------------
__global__ void __launch_bounds__(256, 2)
proj_mega(const float* __restrict__ bq, const float* __restrict__ bk,
          const float* __restrict__ bv, const float* __restrict__ pbu)
{
    extern __shared__ char smc[];
    const int id = blockIdx.x;
    int op, mi, ni;
    if (id < 768) { op = id >> 8; const int r = id & 255; mi = r >> 3; ni = r & 7; }
    else          { op = 3; const int r = id - 768; mi = r >> 3; ni = r & 7; }

    const int inoff = (op == 0) ? OIQ : (op == 1) ? OIK : (op == 2) ? OIV : OIP;
    const int woff  = op * 1048576;
    const int M = (op == 3) ? P_DIM : BT_DIM;
    const int m0 = mi * 128, n0 = ni * 128;

    float acc[4][4][4] = {};
    gemm_core_f16(g_i16h + inoff, g_i16l + inoff, g_w16 + woff, m0, n0, M, smc, acc);

    const int lane = threadIdx.x & 31, wid = threadIdx.x >> 5;
    const int g = lane >> 2, tg = lane & 3, wm = wid >> 2, wn = wid & 3;
    __half* gh = (op == 1) ? g_k16 : (op == 2) ? g_v16 : g_p16;

    #pragma unroll
    for (int mt = 0; mt < 4; mt++) {
        const int r0 = m0 + wm * 64 + mt * 16 + g;
        const int r1 = r0 + 8;
        #pragma unroll
        for (int nt = 0; nt < 4; nt++) {
            const int col = n0 + wn * 32 + nt * 8 + 2 * tg;
            float b0 = 0.f, b1 = 0.f;
            if (op == 0)      { b0 = bq[col] + pbu[col]; b1 = bq[col + 1] + pbu[col + 1]; }
            else if (op == 1) { b0 = bk[col]; b1 = bk[col + 1]; }
            else if (op == 2) { b0 = bv[col]; b1 = bv[col + 1]; }
            float x0 = acc[mt][nt][0] + b0, x1 = acc[mt][nt][1] + b1;
            float x2 = acc[mt][nt][2] + b0, x3 = acc[mt][nt][3] + b1;
            if (op == 0) {
                x0 *= 0.125f; x1 *= 0.125f; x2 *= 0.125f; x3 *= 0.125f;
                if (r0 < M) st_pair_split_h(g_qu16h, g_qu16l, (size_t)r0 * C_DIM + col, x0, x1);
                if (r1 < M) st_pair_split_h(g_qu16h, g_qu16l, (size_t)r1 * C_DIM + col, x2, x3);
            } else {
                if (r0 < M)
                    *(__half2*)(gh + (size_t)r0 * C_DIM + col) =
                        __halves2half2(__float2half_rn(x0), __float2half_rn(x1));
                if (r1 < M)
                    *(__half2*)(gh + (size_t)r1 * C_DIM + col) =
                        __halves2half2(__float2half_rn(x2), __float2half_rn(x3));
            }
        }
    }
}

// Output projection: A = attention out (fp16 hi/lo), writes fp32 d_out.
__global__ void __launch_bounds__(256, 2)
gemm_out(const float* __restrict__ bias, float* __restrict__ Cout)
{
    extern __shared__ char smc[];
    const int mi = blockIdx.x >> 3, ni = blockIdx.x & 7;
    const int m0 = mi * 128, n0 = ni * 128;
    float acc[4][4][4] = {};
    gemm_core_f16(g_x16h, g_x16l, g_w16 + OWO, m0, n0, BT_DIM, smc, acc);

    const int lane = threadIdx.x & 31, wid = threadIdx.x >> 5;
    const int g = lane >> 2, tg = lane & 3, wm = wid >> 2, wn = wid & 3;
    #pragma unroll
    for (int mt = 0; mt < 4; mt++) {
        const int r0 = m0 + wm * 64 + mt * 16 + g;
        #pragma unroll
        for (int nt = 0; nt < 4; nt++) {
            const int col = n0 + wn * 32 + nt * 8 + 2 * tg;
            const float b0 = bias[col], b1 = bias[col + 1];
            *(float2*)(Cout + (size_t)r0 * C_DIM + col) =
                make_float2(acc[mt][nt][0] + b0, acc[mt][nt][1] + b1);
            *(float2*)(Cout + (size_t)(r0 + 8) * C_DIM + col) =
                make_float2(acc[mt][nt][2] + b0, acc[mt][nt][3] + b1);
        }
    }
}

// ---------------------------------------------------------------------------
// Attention (fp16x2, R13 choreography): Qu hi+lo; K/band/V hi-only; P hi+lo.
// AC/G/PV all 2 MMAs per product (was 3). Smem 74.5 KB -> 2+ CTAs/SM.
// NOTE: BD fp32 staging aliases the P fp16 tiles ACROSS WARPS — the barrier
// between exp (BD reads) and P stores is mandatory.
// ---------------------------------------------------------------------------
#define ATP 72
#define OQUH 0
#define OQUL 9216
#define OKH  18432
#define OVH  27648
#define OBH  36864
#define OPH  55296
#define OPL  64512
#define OEV  73728
#define ODL  74240
#define ATT_BYTES 74496

__global__ void __launch_bounds__(128)
attn_f16(const float* __restrict__ pbu, const float* __restrict__ pbv)
{
    extern __shared__ char smc[];
    const uint32_t sb = smem_u32(smc);
    const int tid = threadIdx.x;
    const int wid = tid >> 5;
    const int lane = tid & 31;
    const int g = lane >> 2, tg = lane & 3;
    const int t0 = blockIdx.x * 64;
    const int b = (int)blockIdx.y >> 4;
    const int h = (int)blockIdx.y & 15;
    const int row0w = wid * 16;
    const int row0g = row0w + g;
    const int cbase = 48 - row0w;

    // Prologue: G1 = K0 + band0, G2 = QU (hi+lo), G3 = V0
    {
        const int w0 = 960 - t0;
        #pragma unroll
        for (int jj = 0; jj < 4; jj++) {
            const int f = tid + 128 * jj;
            const int row = f >> 3, ch = f & 7;
            cp_async16(sb + OKH + (uint32_t)((row * ATP + ch * 8) * 2),
                       g_k16 + ((size_t)row * B_DIM + b) * C_DIM + h * 64 + ch * 8, true);
        }
        #pragma unroll
        for (int jj = 0; jj < 8; jj++) {
            const int f = tid + 128 * jj;
            const int row = f >> 3, ch = f & 7;
            if (row < 127) {
                const int pr = w0 + row;
                const int slot = pr & 127;
                cp_async16(sb + OBH + (uint32_t)((slot * ATP + ch * 8) * 2),
                           g_p16 + (size_t)pr * C_DIM + h * 64 + ch * 8, true);
            }
        }
        cp_commit();
        #pragma unroll
        for (int jj = 0; jj < 8; jj++) {
            const int f = tid + 128 * jj;
            const int half = f >> 9, rem = f & 511, row = rem >> 3, ch = rem & 7;
            const __half* src = half ? g_qu16l : g_qu16h;
            const uint32_t dst = sb + (half ? OQUL : OQUH);
            cp_async16(dst + (uint32_t)((row * ATP + ch * 8) * 2),
                       src + ((size_t)(t0 + row) * B_DIM + b) * C_DIM + h * 64 + ch * 8, true);
        }
        cp_commit();
        #pragma unroll
        for (int jj = 0; jj < 4; jj++) {
            const int f = tid + 128 * jj;
            const int row = f >> 3, ch = f & 7;
            cp_async16(sb + OVH + (uint32_t)((row * ATP + ch * 8) * 2),
                       g_v16 + ((size_t)row * B_DIM + b) * C_DIM + h * 64 + ch * 8, true);
        }
        cp_commit();
    }

    if (tid < 64)
        ((float*)(smc + ODL))[tid] = (pbv[h * 64 + tid] - pbu[h * 64 + tid]) * 0.125f;

    cp_wait<1>();      // K0, band0, QU arrived (V0 pending)
    __syncthreads();

    // Loop-invariant QU fragments
    uint32_t quh[4][4], qul[4][4];
    #pragma unroll
    for (int k = 0; k < 4; k++) {
        const uint32_t aa = a_addr(sb + OQUH, row0w, k * 16, lane, ATP);
        ldsm_x4(quh[k], aa);
        ldsm_x4(qul[k], aa + (OQUL - OQUH));
    }

    float oacc[8][4];
    #pragma unroll
    for (int nt = 0; nt < 8; nt++)
        #pragma unroll
        for (int r = 0; r < 4; r++) oacc[nt][r] = 0.f;
    float lp0 = 0.f, lp1 = 0.f;

    for (int it = 0; it < 16; it++) {
        const int s0 = it * 64;
        const int off = (s0 - t0 + 960) & 127;
        const int s0n = (s0 + 64 < T_DIM) ? s0 + 64 : s0;
        const int wnx = s0n - t0 + 960;

        cp_wait<1>();
        __syncthreads();

        // e[c] = delta . band[c]  (band hi only)
        if (tid < 127) {
            const int phys = (off + tid) & 127;
            const __half2* bh2 = (const __half2*)((__half*)(smc + OBH) + phys * ATP);
            const float2* dl2 = (const float2*)(smc + ODL);
            float s = 0.f;
            #pragma unroll
            for (int d2 = 0; d2 < 32; d2++) {
                const __half2 hh = bh2[d2];
                const float2 dv = dl2[d2];
                s = fmaf(__half2float(hh.x), dv.x, fmaf(__half2float(hh.y), dv.y, s));
            }
            ((float*)(smc + OEV))[tid] = s;
        }

        // Stage 1: AC = Qu @ K^T  (2 MMAs per product)
        float sacc[8][4];
        #pragma unroll
        for (int nt = 0; nt < 8; nt++)
            #pragma unroll
            for (int r = 0; r < 4; r++) sacc[nt][r] = 0.f;
        #pragma unroll
        for (int k = 0; k < 4; k++) {
            #pragma unroll
            for (int p = 0; p < 4; p++) {
                uint32_t kh4[4];
                ldsm_x4(kh4, b_addr(sb + OKH, p * 16, k * 16, lane, ATP));
                mma_fp16(sacc[2 * p],     quh[k], kh4);
                mma_fp16(sacc[2 * p],     qul[k], kh4);
                mma_fp16(sacc[2 * p + 1], quh[k], kh4 + 2);
                mma_fp16(sacc[2 * p + 1], qul[k], kh4 + 2);
            }
        }
        __syncthreads();   // K reads done; EV visible

        // prefetch K_{i+1}
        #pragma unroll
        for (int jj = 0; jj < 4; jj++) {
            const int f = tid + 128 * jj;
            const int row = f >> 3, ch = f & 7;
            cp_async16(sb + OKH + (uint32_t)((row * ATP + ch * 8) * 2),
                       g_k16 + ((size_t)(s0n + row) * B_DIM + b) * C_DIM + h * 64 + ch * 8, true);
        }
        cp_commit();

        // Stage 2: windowed G = Qu @ band^T (5 p-tiles), scatter bd into BD
        float gacc[10][4];
        #pragma unroll
        for (int nt = 0; nt < 10; nt++)
            #pragma unroll
            for (int r = 0; r < 4; r++) gacc[nt][r] = 0.f;
        #pragma unroll
        for (int k = 0; k < 4; k++) {
            #pragma unroll
            for (int p = 0; p < 5; p++) {
                const int basep = (off + cbase + p * 16) & 127;
                uint32_t bh4[4];
                ldsm_x4(bh4, b_addr(sb + OBH, basep, k * 16, lane, ATP));
                mma_fp16(gacc[2 * p],     quh[k], bh4);
                mma_fp16(gacc[2 * p],     qul[k], bh4);
                mma_fp16(gacc[2 * p + 1], quh[k], bh4 + 2);
                mma_fp16(gacc[2 * p + 1], qul[k], bh4 + 2);
            }
        }
        {
            float* BD = (float*)(smc + OPH);
            const float* EV = (const float*)(smc + OEV);
            #pragma unroll
            for (int nt = 0; nt < 10; nt++)
                #pragma unroll
                for (int r2 = 0; r2 < 2; r2++) {
                    const int t = row0g + 8 * r2;
                    #pragma unroll
                    for (int cc = 0; cc < 2; cc++) {
                        const int c = cbase + nt * 8 + 2 * tg + cc;
                        const int s = c - 63 + t;
                        if (s >= 0 && s < 64)
                            BD[t * 68 + s] = gacc[nt][r2 * 2 + cc] + EV[c];
                    }
                }
        }
        __syncthreads();   // band reads done (before band prefetch); BD visible

        // prefetch band_{i+1}: 64 new p-rows
        #pragma unroll
        for (int jj = 0; jj < 4; jj++) {
            const int f = tid + 128 * jj;
            const int row = f >> 3, ch = f & 7;
            const int pr = wnx + 63 + row;
            const int slot = pr & 127;
            cp_async16(sb + OBH + (uint32_t)((slot * ATP + ch * 8) * 2),
                       g_p16 + (size_t)pr * C_DIM + h * 64 + ch * 8, true);
        }
        cp_commit();

        // Stage 3: P = exp(ac + bd)
        const float* BD = (const float*)(smc + OPH);
        float pval[8][4];
        #pragma unroll
        for (int nt = 0; nt < 8; nt++)
            #pragma unroll
            for (int r2 = 0; r2 < 2; r2++) {
                const int t = row0g + 8 * r2;
                #pragma unroll
                for (int cc = 0; cc < 2; cc++) {
                    const int s = nt * 8 + 2 * tg + cc;
                    float v = sacc[nt][r2 * 2 + cc] + BD[t * 68 + s];
                    v = __expf(fminf(v, 10.f));
                    pval[nt][r2 * 2 + cc] = v;
                    if (r2 == 0) lp0 += v; else lp1 += v;
                }
            }
        __syncthreads();   // MANDATORY: BD aliases P tiles across warps
        {
            __half* Ph = (__half*)(smc + OPH);
            __half* Pl = (__half*)(smc + OPL);
            #pragma unroll
            for (int nt = 0; nt < 8; nt++)
                #pragma unroll
                for (int r2 = 0; r2 < 2; r2++) {
                    const int t = row0g + 8 * r2;
                    const int s = nt * 8 + 2 * tg;
                    st_pair_split_h(Ph, Pl, (size_t)(t * ATP + s),
                                    pval[nt][r2 * 2], pval[nt][r2 * 2 + 1]);
                }
        }
        cp_wait<2>();      // V_i arrived
        __syncthreads();   // P + V visible

        // Stage 4: O += P @ V  (P hi+lo, V hi only)
        #pragma unroll
        for (int k = 0; k < 4; k++) {
            const uint32_t pa = a_addr(sb + OPH, row0w, k * 16, lane, ATP);
            uint32_t aph[4], apl[4];
            ldsm_x4(aph, pa);
            ldsm_x4(apl, pa + (OPL - OPH));
            #pragma unroll
            for (int p = 0; p < 4; p++) {
                uint32_t vh4[4];
                ldsm_x4t(vh4, a_addr(sb + OVH, k * 16, p * 16, lane, ATP));
                mma_fp16(oacc[2 * p],     aph, vh4);
                mma_fp16(oacc[2 * p],     apl, vh4);
                mma_fp16(oacc[2 * p + 1], aph, vh4 + 2);
                mma_fp16(oacc[2 * p + 1], apl, vh4 + 2);
            }
        }
        __syncthreads();   // V reads done

        // prefetch V_{i+1}
        #pragma unroll
        for (int jj = 0; jj < 4; jj++) {
            const int f = tid + 128 * jj;
            const int row = f >> 3, ch = f & 7;
            cp_async16(sb + OVH + (uint32_t)((row * ATP + ch * 8) * 2),
                       g_v16 + ((size_t)(s0n + row) * B_DIM + b) * C_DIM + h * 64 + ch * 8, true);
        }
        cp_commit();
    }
    cp_wait<0>();

    lp0 += __shfl_xor_sync(0xffffffffu, lp0, 1);
    lp0 += __shfl_xor_sync(0xffffffffu, lp0, 2);
    lp1 += __shfl_xor_sync(0xffffffffu, lp1, 1);
    lp1 += __shfl_xor_sync(0xffffffffu, lp1, 2);
    const float inv0 = 1.f / lp0;
    const float inv1 = 1.f / lp1;

    #pragma unroll
    for (int nt = 0; nt < 8; nt++) {
        const int col = h * 64 + nt * 8 + 2 * tg;
        const size_t o0 = ((size_t)(t0 + row0g) * B_DIM + b) * C_DIM + col;
        const size_t o1 = ((size_t)(t0 + row0g + 8) * B_DIM + b) * C_DIM + col;
        st_pair_split_h(g_x16h, g_x16l, o0, oacc[nt][0] * inv0, oacc[nt][1] * inv0);
        st_pair_split_h(g_x16h, g_x16l, o1, oacc[nt][2] * inv1, oacc[nt][3] * inv1);
    }
}

// ---------------------------------------------------------------------------
// Launch
// ---------------------------------------------------------------------------
extern "C" void kernel_launch(void* const* d_in, const int* in_sizes, int n_in,
                              void* d_out, int out_size)
{
    const float* query   = (const float*)d_in[0];
    const float* key     = (const float*)d_in[1];
    const float* value   = (const float*)d_in[2];
    const float* pos_emb = (const float*)d_in[3];
    const float* Wq      = (const float*)d_in[4];
    const float* bq      = (const float*)d_in[5];
    const float* Wk      = (const float*)d_in[6];
    const float* bk      = (const float*)d_in[7];
    const float* Wv      = (const float*)d_in[8];
    const float* bv      = (const float*)d_in[9];
    const float* Wp      = (const float*)d_in[10];
    const float* Wo      = (const float*)d_in[11];
    const float* bo      = (const float*)d_in[12];
    const float* pbu     = (const float*)d_in[13];
    const float* pbv     = (const float*)d_in[14];
    float* out = (float*)d_out;

    cudaFuncSetAttribute(proj_mega, cudaFuncAttributeMaxDynamicSharedMemorySize, FSM_BYTES);
    cudaFuncSetAttribute(gemm_out,  cudaFuncAttributeMaxDynamicSharedMemorySize, FSM_BYTES);
    cudaFuncSetAttribute(attn_f16,  cudaFuncAttributeMaxDynamicSharedMemorySize, ATT_BYTES);

    split_all<<<19455, 256>>>((const float4*)Wq, (const float4*)Wk, (const float4*)Wv,
                              (const float4*)Wp, (const float4*)Wo,
                              (const float4*)query, (const float4*)key,
                              (const float4*)value, (const float4*)pos_emb);

    proj_mega<<<896, 256, FSM_BYTES>>>(bq, bk, bv, pbu);
    attn_f16<<<dim3(16, 64), 128, ATT_BYTES>>>(pbu, pbv);
    gemm_out<<<256, 256, FSM_BYTES>>>(bo, out);
}

// round 15
// speedup vs baseline: 1.7365x; 1.1243x over previous
#include <cuda_runtime.h>
#include <cuda_bf16.h>
#include <cuda_fp16.h>
#include <math_constants.h>
#include <cstdint>

// Problem constants
#define T_DIM 1024
#define B_DIM 4
#define C_DIM 1024
#define H_DIM 16
#define D_DIM 64
#define P_DIM 2047
#define BT_DIM (B_DIM * T_DIM)

// Scratch (device globals). Row order m = t*B + b ([T,B,C] natural).
__device__ __half g_qu16h[BT_DIM * C_DIM];   // (q@Wq+bq+pbu)*0.125 hi
__device__ __half g_qu16l[BT_DIM * C_DIM];   // lo
__device__ __half g_k16[BT_DIM * C_DIM];     // hi only
__device__ __half g_v16[BT_DIM * C_DIM];     // hi only
__device__ __half g_p16[P_DIM * C_DIM];      // hi only
__device__ __half g_x16h[BT_DIM * C_DIM];    // attention out hi/lo (fp16)
__device__ __half g_x16l[BT_DIM * C_DIM];
#define OWQ 0
#define OWK 1048576
#define OWV 2097152
#define OWP 3145728
#define OWO 4194304
__device__ __half g_w16[5 * 1048576];        // weights, fp16 hi only
#define OIQ 0
#define OIK 4194304
#define OIV 8388608
#define OIP 12582912
__device__ __half g_i16h[14679040];          // inputs, fp16 hi
__device__ __half g_i16l[4194304];           // q input lo only

// ---------------------------------------------------------------------------
// Helpers
// ---------------------------------------------------------------------------
__device__ __forceinline__ uint32_t smem_u32(const void* p) {
    uint32_t a;
    asm("{ .reg .u64 t; cvta.to.shared.u64 t, %1; cvt.u32.u64 %0, t; }" : "=r"(a) : "l"(p));
    return a;
}
__device__ __forceinline__ void cp_async16(uint32_t saddr, const void* gptr, bool pred) {
    const int sz = pred ? 16 : 0;
    asm volatile("cp.async.cg.shared.global [%0], [%1], 16, %2;"
                 :: "r"(saddr), "l"(gptr), "r"(sz));
}
__device__ __forceinline__ void cp_commit() { asm volatile("cp.async.commit_group;"); }
template <int N>
__device__ __forceinline__ void cp_wait() { asm volatile("cp.async.wait_group %0;" :: "n"(N)); }

__device__ __forceinline__ void ldsm_x4(uint32_t* r, uint32_t a) {
    asm volatile("ldmatrix.sync.aligned.m8n8.x4.shared.b16 {%0,%1,%2,%3}, [%4];"
                 : "=r"(r[0]), "=r"(r[1]), "=r"(r[2]), "=r"(r[3]) : "r"(a));
}
__device__ __forceinline__ void ldsm_x4t(uint32_t* r, uint32_t a) {
    asm volatile("ldmatrix.sync.aligned.m8n8.x4.trans.shared.b16 {%0,%1,%2,%3}, [%4];"
                 : "=r"(r[0]), "=r"(r[1]), "=r"(r[2]), "=r"(r[3]) : "r"(a));
}
__device__ __forceinline__ void mma_fp16(float* c, const uint32_t* a, const uint32_t* b) {
    asm volatile("mma.sync.aligned.m16n8k16.row.col.f32.f16.f16.f32 "
                 "{%0,%1,%2,%3}, {%4,%5,%6,%7}, {%8,%9}, {%0,%1,%2,%3};"
                 : "+f"(c[0]), "+f"(c[1]), "+f"(c[2]), "+f"(c[3])
                 : "r"(a[0]), "r"(a[1]), "r"(a[2]), "r"(a[3]), "r"(b[0]), "r"(b[1]));
}
__device__ __forceinline__ uint32_t uh16(__half h) { return (uint32_t)__half_as_ushort(h); }

__device__ __forceinline__ uint32_t a_addr(uint32_t base, int row0, int k0, int lane, int pitch) {
    const int row = row0 + (lane & 15);
    const int col = k0 + ((lane >> 4) << 3);
    return base + (uint32_t)((row * pitch + col) * 2);
}
__device__ __forceinline__ uint32_t b_addr(uint32_t base, int n0, int k0, int lane, int pitch) {
    const int row = n0 + (lane & 7) + ((lane >> 4) << 3);
    const int col = k0 + (lane & 8);
    return base + (uint32_t)((row * pitch + col) * 2);
}

__device__ __forceinline__ uint32_t sw64(int row, int chunk) {
    return (uint32_t)((row << 6) + (((chunk ^ (row >> 1)) & 3) << 4));
}

__device__ __forceinline__ void st_pair_split_h(__half* gh, __half* gl,
                                                size_t off, float x0, float x1) {
    __half h0 = __float2half_rn(x0), h1 = __float2half_rn(x1);
    __half l0 = __float2half_rn(x0 - __half2float(h0));
    __half l1 = __float2half_rn(x1 - __half2float(h1));
    *(__half2*)(gh + off) = __halves2half2(h0, h1);
    *(__half2*)(gl + off) = __halves2half2(l0, l1);
}

// ---------------------------------------------------------------------------
// Merged setup: weights -> fp16 hi; q input -> hi+lo; k/v/p inputs -> hi only.
// ---------------------------------------------------------------------------
__global__ void __launch_bounds__(256)
split_all(const float4* __restrict__ Wq, const float4* __restrict__ Wk,
          const float4* __restrict__ Wv, const float4* __restrict__ Wp,
          const float4* __restrict__ Wo,
          const float4* __restrict__ q, const float4* __restrict__ k,
          const float4* __restrict__ v, const float4* __restrict__ p)
{
    const int bid = blockIdx.x;
    if (bid < 5120) {
        const int w = bid >> 10;
        const float4* src = (w == 0) ? Wq : (w == 1) ? Wk : (w == 2) ? Wv : (w == 3) ? Wp : Wo;
        const int i = (bid & 1023) * 256 + threadIdx.x;
        if (i >= 262144) return;
        const float4 val = src[i];
        const uint32_t h0 = uh16(__float2half_rn(val.x)), h1 = uh16(__float2half_rn(val.y));
        const uint32_t h2 = uh16(__float2half_rn(val.z)), h3 = uh16(__float2half_rn(val.w));
        uint2 H; H.x = (h1 << 16) | h0; H.y = (h3 << 16) | h2;
        ((uint2*)(g_w16 + w * 1048576))[i] = H;
        return;
    }
    if (bid < 9216) {  // q: hi + lo
        const int i = (bid - 5120) * 256 + threadIdx.x;
        if (i >= 1048576) return;
        const float4 val = q[i];
        __half h0 = __float2half_rn(val.x), h1 = __float2half_rn(val.y);
        __half h2 = __float2half_rn(val.z), h3 = __float2half_rn(val.w);
        __half l0 = __float2half_rn(val.x - __half2float(h0));
        __half l1 = __float2half_rn(val.y - __half2float(h1));
        __half l2 = __float2half_rn(val.z - __half2float(h2));
        __half l3 = __float2half_rn(val.w - __half2float(h3));
        uint2 H, L;
        H.x = (uh16(h1) << 16) | uh16(h0); H.y = (uh16(h3) << 16) | uh16(h2);
        L.x = (uh16(l1) << 16) | uh16(l0); L.y = (uh16(l3) << 16) | uh16(l2);
        ((uint2*)(g_i16h + OIQ))[i] = H;
        ((uint2*)g_i16l)[i] = L;
        return;
    }
    // k, v, p: hi only
    const float4* src;
    __half* dh;
    int i, n4;
    if (bid < 13312) {
        src = k; dh = g_i16h + OIK; i = (bid - 9216) * 256 + threadIdx.x; n4 = 1048576;
    } else if (bid < 17408) {
        src = v; dh = g_i16h + OIV; i = (bid - 13312) * 256 + threadIdx.x; n4 = 1048576;
    } else {
        src = p; dh = g_i16h + OIP; i = (bid - 17408) * 256 + threadIdx.x; n4 = 524032;
    }
    if (i >= n4) return;
    const float4 val = src[i];
    const uint32_t h0 = uh16(__float2half_rn(val.x)), h1 = uh16(__float2half_rn(val.y));
    const uint32_t h2 = uh16(__float2half_rn(val.z)), h3 = uh16(__float2half_rn(val.w));
    uint2 H; H.x = (h1 << 16) | h0; H.y = (h3 << 16) | h2;
    ((uint2*)dh)[i] = H;
}

// ---------------------------------------------------------------------------
// fp16 GEMM core, templated on A-lo usage.
// USE_ALO=true:  C = (Ah+Al) @ Bh^T (2 MMAs/product), stage = 3 tiles.
// USE_ALO=false: C = Ah @ Bh^T      (1 MMA/product), stage = 2 tiles.
// CTA 128x128, 8 warps (2x4), warp 64x32. 3-stage pipeline, swizzled smem.
// ---------------------------------------------------------------------------
#define FTS 8192
#define FSM_BYTES (3 * 3 * FTS)   // max (USE_ALO layout)

template <bool USE_ALO>
__device__ __forceinline__ void gemm_core_f16(
    const __half* __restrict__ Ah, const __half* __restrict__ Al,
    const __half* __restrict__ Bh,
    int m0, int n0, int M, char* smc, float acc[4][4][4])
{
    const int NT = USE_ALO ? 3 : 2;         // tiles per stage
    const uint32_t FSTG = (uint32_t)(NT * FTS);
    const int NG = USE_ALO ? 6 : 4;         // granules per thread per chunk
    const uint32_t sb = smem_u32(smc);
    const int tid = threadIdx.x;
    const int lane = tid & 31;
    const int wid = tid >> 5;
    const int wm = wid >> 2, wn = wid & 3;

    const __half* gsrc[6];
    uint32_t soff[6];
    #pragma unroll
    for (int j = 0; j < NG; j++) {
        const int f = tid + 256 * j;
        const int tile = f >> 9;             // 0=Ah, 1=Al (if used) else Bh
        const int idx = f & 511;
        const int row = idx >> 2;
        const int ch = idx & 3;
        const bool isA = USE_ALO ? (tile < 2) : (tile < 1);
        int r = (isA ? m0 : n0) + row;
        if (isA && r > M - 1) r = M - 1;
        const __half* base;
        if (USE_ALO) base = (tile == 0) ? Ah : (tile == 1) ? Al : Bh;
        else         base = (tile == 0) ? Ah : Bh;
        gsrc[j] = base + (size_t)r * C_DIM + ch * 8;
        soff[j] = (uint32_t)(tile * FTS) + sw64(row, ch);
    }

    #pragma unroll
    for (int j = 0; j < NG; j++) cp_async16(sb + soff[j], gsrc[j], true);
    cp_commit();
    #pragma unroll
    for (int j = 0; j < NG; j++) cp_async16(sb + FSTG + soff[j], gsrc[j] + 32, true);
    cp_commit();

    const uint32_t bh_off = (uint32_t)((NT - 1) * FTS);  // Bh tile offset in stage
    int stage = 0;
    for (int kc = 0; kc < 32; kc++) {
        if (kc < 31) cp_wait<1>(); else cp_wait<0>();
        __syncthreads();
        if (kc + 2 < 32) {
            const int pst = (stage + 2 >= 3) ? stage - 1 : stage + 2;
            const uint32_t pb = sb + (uint32_t)pst * FSTG;
            const int kof = (kc + 2) * 32;
            #pragma unroll
            for (int j = 0; j < NG; j++)
                cp_async16(pb + soff[j], gsrc[j] + kof, true);
            cp_commit();
        }
        const uint32_t sab = sb + (uint32_t)stage * FSTG;
        #pragma unroll
        for (int ks = 0; ks < 2; ks++) {
            const int c0 = ks * 2;
            uint32_t bh[2][4];
            #pragma unroll
            for (int p = 0; p < 2; p++) {
                const int brow = wn * 32 + p * 16 + (lane & 7) + ((lane >> 4) << 3);
                const int bch = c0 + ((lane >> 3) & 1);
                ldsm_x4(bh[p], sab + bh_off + sw64(brow, bch));
            }
            #pragma unroll
            for (int mt = 0; mt < 4; mt++) {
                const int arow = wm * 64 + mt * 16 + (lane & 15);
                const int ach = c0 + (lane >> 4);
                const uint32_t aa = sab + sw64(arow, ach);
                uint32_t ah[4], al[4];
                ldsm_x4(ah, aa);
                if (USE_ALO) ldsm_x4(al, aa + FTS);
                #pragma unroll
                for (int nt = 0; nt < 4; nt++) {
                    const uint32_t* bhp = &bh[nt >> 1][(nt & 1) * 2];
                    mma_fp16(acc[mt][nt], ah, bhp);
                    if (USE_ALO) mma_fp16(acc[mt][nt], al, bhp);
                }
            }
        }
        stage = (stage + 1 >= 3) ? 0 : stage + 1;
    }
}

// ---------------------------------------------------------------------------
// Mega projection: q,k,v,p in one launch (896 CTAs, tile 128x128).
// op0 (q): hi+lo core; ops 1-3 (k,v,p): hi-only core.
// ---------------------------------------------------------------------------
__global__ void __launch_bounds__(256, 2)
proj_mega(const float* __restrict__ bq, const float* __restrict__ bk,
          const float* __restrict__ bv, const float* __restrict__ pbu)
{
    extern __shared__ char smc[];
    const int id = blockIdx.x;
    int op, mi, ni;
    if (id < 768) { op = id >> 8; const int r = id & 255; mi = r >> 3; ni = r & 7; }
    else          { op = 3; const int r = id - 768; mi = r >> 3; ni = r & 7; }

    const int inoff = (op == 0) ? OIQ : (op == 1) ? OIK : (op == 2) ? OIV : OIP;
    const int woff  = op * 1048576;
    const int M = (op == 3) ? P_DIM : BT_DIM;
    const int m0 = mi * 128, n0 = ni * 128;

    float acc[4][4][4] = {};
    if (op == 0)
        gemm_core_f16<true>(g_i16h + OIQ, g_i16l, g_w16 + woff, m0, n0, M, smc, acc);
    else
        gemm_core_f16<false>(g_i16h + inoff, nullptr, g_w16 + woff, m0, n0, M, smc, acc);

    const int lane = threadIdx.x & 31, wid = threadIdx.x >> 5;
    const int g = lane >> 2, tg = lane & 3, wm = wid >> 2, wn = wid & 3;
    __half* gh = (op == 1) ? g_k16 : (op == 2) ? g_v16 : g_p16;

    #pragma unroll
    for (int mt = 0; mt < 4; mt++) {
        const int r0 = m0 + wm * 64 + mt * 16 + g;
        const int r1 = r0 + 8;
        #pragma unroll
        for (int nt = 0; nt < 4; nt++) {
            const int col = n0 + wn * 32 + nt * 8 + 2 * tg;
            float b0 = 0.f, b1 = 0.f;
            if (op == 0)      { b0 = bq[col] + pbu[col]; b1 = bq[col + 1] + pbu[col + 1]; }
            else if (op == 1) { b0 = bk[col]; b1 = bk[col + 1]; }
            else if (op == 2) { b0 = bv[col]; b1 = bv[col + 1]; }
            float x0 = acc[mt][nt][0] + b0, x1 = acc[mt][nt][1] + b1;
            float x2 = acc[mt][nt][2] + b0, x3 = acc[mt][nt][3] + b1;
            if (op == 0) {
                x0 *= 0.125f; x1 *= 0.125f; x2 *= 0.125f; x3 *= 0.125f;
                if (r0 < M) st_pair_split_h(g_qu16h, g_qu16l, (size_t)r0 * C_DIM + col, x0, x1);
                if (r1 < M) st_pair_split_h(g_qu16h, g_qu16l, (size_t)r1 * C_DIM + col, x2, x3);
            } else {
                if (r0 < M)
                    *(__half2*)(gh + (size_t)r0 * C_DIM + col) =
                        __halves2half2(__float2half_rn(x0), __float2half_rn(x1));
                if (r1 < M)
                    *(__half2*)(gh + (size_t)r1 * C_DIM + col) =
                        __halves2half2(__float2half_rn(x2), __float2half_rn(x3));
            }
        }
    }
}

// Output projection: A = attention out (fp16 hi/lo), writes fp32 d_out.
__global__ void __launch_bounds__(256, 2)
gemm_out(const float* __restrict__ bias, float* __restrict__ Cout)
{
    extern __shared__ char smc[];
    const int mi = blockIdx.x >> 3, ni = blockIdx.x & 7;
    const int m0 = mi * 128, n0 = ni * 128;
    float acc[4][4][4] = {};
    gemm_core_f16<true>(g_x16h, g_x16l, g_w16 + OWO, m0, n0, BT_DIM, smc, acc);

    const int lane = threadIdx.x & 31, wid = threadIdx.x >> 5;
    const int g = lane >> 2, tg = lane & 3, wm = wid >> 2, wn = wid & 3;
    #pragma unroll
    for (int mt = 0; mt < 4; mt++) {
        const int r0 = m0 + wm * 64 + mt * 16 + g;
        #pragma unroll
        for (int nt = 0; nt < 4; nt++) {
            const int col = n0 + wn * 32 + nt * 8 + 2 * tg;
            const float b0 = bias[col], b1 = bias[col + 1];
            *(float2*)(Cout + (size_t)r0 * C_DIM + col) =
                make_float2(acc[mt][nt][0] + b0, acc[mt][nt][1] + b1);
            *(float2*)(Cout + (size_t)(r0 + 8) * C_DIM + col) =
                make_float2(acc[mt][nt][2] + b0, acc[mt][nt][3] + b1);
        }
    }
}

// ---------------------------------------------------------------------------
// Attention (fp16, R14 choreography): Qu hi+lo; K/band/V hi; P hi only (NEW).
// AC/G 2 MMAs per product; PV 1 MMA per product.
// NOTE: BD fp32 staging aliases the P fp16 tile ACROSS WARPS — the barrier
// between exp (BD reads) and P stores is mandatory.
// ---------------------------------------------------------------------------
#define ATP 72
#define OQUH 0
#define OQUL 9216
#define OKH  18432
#define OVH  27648
#define OBH  36864
#define OPH  55296
#define OEV  73728
#define ODL  74240
#define ATT_BYTES 74496

__global__ void __launch_bounds__(128)
attn_f16(const float* __restrict__ pbu, const float* __restrict__ pbv)
{
    extern __shared__ char smc[];
    const uint32_t sb = smem_u32(smc);
    const int tid = threadIdx.x;
    const int wid = tid >> 5;
    const int lane = tid & 31;
    const int g = lane >> 2, tg = lane & 3;
    const int t0 = blockIdx.x * 64;
    const int b = (int)blockIdx.y >> 4;
    const int h = (int)blockIdx.y & 15;
    const int row0w = wid * 16;
    const int row0g = row0w + g;
    const int cbase = 48 - row0w;

    // Prologue: G1 = K0 + band0, G2 = QU (hi+lo), G3 = V0
    {
        const int w0 = 960 - t0;
        #pragma unroll
        for (int jj = 0; jj < 4; jj++) {
            const int f = tid + 128 * jj;
            const int row = f >> 3, ch = f & 7;
            cp_async16(sb + OKH + (uint32_t)((row * ATP + ch * 8) * 2),
                       g_k16 + ((size_t)row * B_DIM + b) * C_DIM + h * 64 + ch * 8, true);
        }
        #pragma unroll
        for (int jj = 0; jj < 8; jj++) {
            const int f = tid + 128 * jj;
            const int row = f >> 3, ch = f & 7;
            if (row < 127) {
                const int pr = w0 + row;
                const int slot = pr & 127;
                cp_async16(sb + OBH + (uint32_t)((slot * ATP + ch * 8) * 2),
                           g_p16 + (size_t)pr * C_DIM + h * 64 + ch * 8, true);
            }
        }
        cp_commit();
        #pragma unroll
        for (int jj = 0; jj < 8; jj++) {
            const int f = tid + 128 * jj;
            const int half = f >> 9, rem = f & 511, row = rem >> 3, ch = rem & 7;
            const __half* src = half ? g_qu16l : g_qu16h;
            const uint32_t dst = sb + (half ? OQUL : OQUH);
            cp_async16(dst + (uint32_t)((row * ATP + ch * 8) * 2),
                       src + ((size_t)(t0 + row) * B_DIM + b) * C_DIM + h * 64 + ch * 8, true);
        }
        cp_commit();
        #pragma unroll
        for (int jj = 0; jj < 4; jj++) {
            const int f = tid + 128 * jj;
            const int row = f >> 3, ch = f & 7;
            cp_async16(sb + OVH + (uint32_t)((row * ATP + ch * 8) * 2),
                       g_v16 + ((size_t)row * B_DIM + b) * C_DIM + h * 64 + ch * 8, true);
        }
        cp_commit();
    }

    if (tid < 64)
        ((float*)(smc + ODL))[tid] = (pbv[h * 64 + tid] - pbu[h * 64 + tid]) * 0.125f;

    cp_wait<1>();
    __syncthreads();

    uint32_t quh[4][4], qul[4][4];
    #pragma unroll
    for (int k = 0; k < 4; k++) {
        const uint32_t aa = a_addr(sb + OQUH, row0w, k * 16, lane, ATP);
        ldsm_x4(quh[k], aa);
        ldsm_x4(qul[k], aa + (OQUL - OQUH));
    }

    float oacc[8][4];
    #pragma unroll
    for (int nt = 0; nt < 8; nt++)
        #pragma unroll
        for (int r = 0; r < 4; r++) oacc[nt][r] = 0.f;
    float lp0 = 0.f, lp1 = 0.f;

    for (int it = 0; it < 16; it++) {
        const int s0 = it * 64;
        const int off = (s0 - t0 + 960) & 127;
        const int s0n = (s0 + 64 < T_DIM) ? s0 + 64 : s0;
        const int wnx = s0n - t0 + 960;

        cp_wait<1>();
        __syncthreads();

        // e[c] = delta . band[c]
        if (tid < 127) {
            const int phys = (off + tid) & 127;
            const __half2* bh2 = (const __half2*)((__half*)(smc + OBH) + phys * ATP);
            const float2* dl2 = (const float2*)(smc + ODL);
            float s = 0.f;
            #pragma unroll
            for (int d2 = 0; d2 < 32; d2++) {
                const __half2 hh = bh2[d2];
                const float2 dv = dl2[d2];
                s = fmaf(__half2float(hh.x), dv.x, fmaf(__half2float(hh.y), dv.y, s));
            }
            ((float*)(smc + OEV))[tid] = s;
        }

        // Stage 1: AC = Qu @ K^T (2 MMAs/product)
        float sacc[8][4];
        #pragma unroll
        for (int nt = 0; nt < 8; nt++)
            #pragma unroll
            for (int r = 0; r < 4; r++) sacc[nt][r] = 0.f;
        #pragma unroll
        for (int k = 0; k < 4; k++) {
            #pragma unroll
            for (int p = 0; p < 4; p++) {
                uint32_t kh4[4];
                ldsm_x4(kh4, b_addr(sb + OKH, p * 16, k * 16, lane, ATP));
                mma_fp16(sacc[2 * p],     quh[k], kh4);
                mma_fp16(sacc[2 * p],     qul[k], kh4);
                mma_fp16(sacc[2 * p + 1], quh[k], kh4 + 2);
                mma_fp16(sacc[2 * p + 1], qul[k], kh4 + 2);
            }
        }
        __syncthreads();   // K reads done; EV visible

        // prefetch K_{i+1}
        #pragma unroll
        for (int jj = 0; jj < 4; jj++) {
            const int f = tid + 128 * jj;
            const int row = f >> 3, ch = f & 7;
            cp_async16(sb + OKH + (uint32_t)((row * ATP + ch * 8) * 2),
                       g_k16 + ((size_t)(s0n + row) * B_DIM + b) * C_DIM + h * 64 + ch * 8, true);
        }
        cp_commit();

        // Stage 2: windowed G = Qu @ band^T (5 p-tiles)
        float gacc[10][4];
        #pragma unroll
        for (int nt = 0; nt < 10; nt++)
            #pragma unroll
            for (int r = 0; r < 4; r++) gacc[nt][r] = 0.f;
        #pragma unroll
        for (int k = 0; k < 4; k++) {
            #pragma unroll
            for (int p = 0; p < 5; p++) {
                const int basep = (off + cbase + p * 16) & 127;
                uint32_t bh4[4];
                ldsm_x4(bh4, b_addr(sb + OBH, basep, k * 16, lane, ATP));
                mma_fp16(gacc[2 * p],     quh[k], bh4);
                mma_fp16(gacc[2 * p],     qul[k], bh4);
                mma_fp16(gacc[2 * p + 1], quh[k], bh4 + 2);
                mma_fp16(gacc[2 * p + 1], qul[k], bh4 + 2);
            }
        }
        {
            float* BD = (float*)(smc + OPH);
            const float* EV = (const float*)(smc + OEV);
            #pragma unroll
            for (int nt = 0; nt < 10; nt++)
                #pragma unroll
                for (int r2 = 0; r2 < 2; r2++) {
                    const int t = row0g + 8 * r2;
                    #pragma unroll
                    for (int cc = 0; cc < 2; cc++) {
                        const int c = cbase + nt * 8 + 2 * tg + cc;
                        const int s = c - 63 + t;
                        if (s >= 0 && s < 64)
                            BD[t * 68 + s] = gacc[nt][r2 * 2 + cc] + EV[c];
                    }
                }
        }
        __syncthreads();   // band reads done (before band prefetch); BD visible

        // prefetch band_{i+1}: 64 new p-rows
        #pragma unroll
        for (int jj = 0; jj < 4; jj++) {
            const int f = tid + 128 * jj;
            const int row = f >> 3, ch = f & 7;
            const int pr = wnx + 63 + row;
            const int slot = pr & 127;
            cp_async16(sb + OBH + (uint32_t)((slot * ATP + ch * 8) * 2),
                       g_p16 + (size_t)pr * C_DIM + h * 64 + ch * 8, true);
        }
        cp_commit();

        // Stage 3: P = exp(ac + bd)
        const float* BD = (const float*)(smc + OPH);
        float pval[8][4];
        #pragma unroll
        for (int nt = 0; nt < 8; nt++)
            #pragma unroll
            for (int r2 = 0; r2 < 2; r2++) {
                const int t = row0g + 8 * r2;
                #pragma unroll
                for (int cc = 0; cc < 2; cc++) {
                    const int s = nt * 8 + 2 * tg + cc;
                    float v = sacc[nt][r2 * 2 + cc] + BD[t * 68 + s];
                    v = __expf(fminf(v, 10.f));
                    pval[nt][r2 * 2 + cc] = v;
                    if (r2 == 0) lp0 += v; else lp1 += v;
                }
            }
        __syncthreads();   // MANDATORY: BD aliases the P tile across warps
        {
            __half* Ph = (__half*)(smc + OPH);
            #pragma unroll
            for (int nt = 0; nt < 8; nt++)
                #pragma unroll
                for (int r2 = 0; r2 < 2; r2++) {
                    const int t = row0g + 8 * r2;
                    const int s = nt * 8 + 2 * tg;
                    *(__half2*)(Ph + (size_t)(t * ATP + s)) =
                        __halves2half2(__float2half_rn(pval[nt][r2 * 2]),
                                       __float2half_rn(pval[nt][r2 * 2 + 1]));
                }
        }
        cp_wait<2>();      // V_i arrived
        __syncthreads();   // P + V visible

        // Stage 4: O += P @ V  (P hi only, V hi only: 1 MMA/product)
        #pragma unroll
        for (int k = 0; k < 4; k++) {
            uint32_t aph[4];
            ldsm_x4(aph, a_addr(sb + OPH, row0w, k * 16, lane, ATP));
            #pragma unroll
            for (int p = 0; p < 4; p++) {
                uint32_t vh4[4];
                ldsm_x4t(vh4, a_addr(sb + OVH, k * 16, p * 16, lane, ATP));
                mma_fp16(oacc[2 * p],     aph, vh4);
                mma_fp16(oacc[2 * p + 1], aph, vh4 + 2);
            }
        }
        __syncthreads();   // V reads done

        // prefetch V_{i+1}
        #pragma unroll
        for (int jj = 0; jj < 4; jj++) {
            const int f = tid + 128 * jj;
            const int row = f >> 3, ch = f & 7;
            cp_async16(sb + OVH + (uint32_t)((row * ATP + ch * 8) * 2),
                       g_v16 + ((size_t)(s0n + row) * B_DIM + b) * C_DIM + h * 64 + ch * 8, true);
        }
        cp_commit();
    }
    cp_wait<0>();

    lp0 += __shfl_xor_sync(0xffffffffu, lp0, 1);
    lp0 += __shfl_xor_sync(0xffffffffu, lp0, 2);
    lp1 += __shfl_xor_sync(0xffffffffu, lp1, 1);
    lp1 += __shfl_xor_sync(0xffffffffu, lp1, 2);
    const float inv0 = 1.f / lp0;
    const float inv1 = 1.f / lp1;

    #pragma unroll
    for (int nt = 0; nt < 8; nt++) {
        const int col = h * 64 + nt * 8 + 2 * tg;
        const size_t o0 = ((size_t)(t0 + row0g) * B_DIM + b) * C_DIM + col;
        const size_t o1 = ((size_t)(t0 + row0g + 8) * B_DIM + b) * C_DIM + col;
        st_pair_split_h(g_x16h, g_x16l, o0, oacc[nt][0] * inv0, oacc[nt][1] * inv0);
        st_pair_split_h(g_x16h, g_x16l, o1, oacc[nt][2] * inv1, oacc[nt][3] * inv1);
    }
}

// ---------------------------------------------------------------------------
// Launch
// ---------------------------------------------------------------------------
extern "C" void kernel_launch(void* const* d_in, const int* in_sizes, int n_in,
                              void* d_out, int out_size)
{
    const float* query   = (const float*)d_in[0];
    const float* key     = (const float*)d_in[1];
    const float* value   = (const float*)d_in[2];
    const float* pos_emb = (const float*)d_in[3];
    const float* Wq      = (const float*)d_in[4];
    const float* bq      = (const float*)d_in[5];
    const float* Wk      = (const float*)d_in[6];
    const float* bk      = (const float*)d_in[7];
    const float* Wv      = (const float*)d_in[8];
    const float* bv      = (const float*)d_in[9];
    const float* Wp      = (const float*)d_in[10];
    const float* Wo      = (const float*)d_in[11];
    const float* bo      = (const float*)d_in[12];
    const float* pbu     = (const float*)d_in[13];
    const float* pbv     = (const float*)d_in[14];
    float* out = (float*)d_out;

    cudaFuncSetAttribute(proj_mega, cudaFuncAttributeMaxDynamicSharedMemorySize, FSM_BYTES);
    cudaFuncSetAttribute(gemm_out,  cudaFuncAttributeMaxDynamicSharedMemorySize, FSM_BYTES);
    cudaFuncSetAttribute(attn_f16,  cudaFuncAttributeMaxDynamicSharedMemorySize, ATT_BYTES);

    split_all<<<19455, 256>>>((const float4*)Wq, (const float4*)Wk, (const float4*)Wv,
                              (const float4*)Wp, (const float4*)Wo,
                              (const float4*)query, (const float4*)key,
                              (const float4*)value, (const float4*)pos_emb);

    proj_mega<<<896, 256, FSM_BYTES>>>(bq, bk, bv, pbu);
    attn_f16<<<dim3(16, 64), 128, ATT_BYTES>>>(pbu, pbv);
    gemm_out<<<256, 256, FSM_BYTES>>>(bo, out);
}

// round 16
// speedup vs baseline: 2.1883x; 1.2602x over previous
#include <cuda_runtime.h>
#include <cuda_fp16.h>
#include <math_constants.h>
#include <cstdint>

// Problem constants
#define T_DIM 1024
#define B_DIM 4
#define C_DIM 1024
#define H_DIM 16
#define D_DIM 64
#define P_DIM 2047
#define BT_DIM (B_DIM * T_DIM)

// Scratch (device globals). Row order m = t*B + b ([T,B,C] natural).
__device__ __half g_qu16[BT_DIM * C_DIM];    // (q@Wq+bq+pbu)*0.125, fp16
__device__ __half g_k16[BT_DIM * C_DIM];
__device__ __half g_v16[BT_DIM * C_DIM];
__device__ __half g_p16[P_DIM * C_DIM];
__device__ __half g_x16[BT_DIM * C_DIM];     // attention out, fp16
#define OWQ 0
#define OWK 1048576
#define OWV 2097152
#define OWP 3145728
#define OWO 4194304
__device__ __half g_w16[5 * 1048576];        // weights, fp16
#define OIQ 0
#define OIK 4194304
#define OIV 8388608
#define OIP 12582912
__device__ __half g_i16[14679040];           // inputs, fp16

// ---------------------------------------------------------------------------
// Helpers
// ---------------------------------------------------------------------------
__device__ __forceinline__ uint32_t smem_u32(const void* p) {
    uint32_t a;
    asm("{ .reg .u64 t; cvta.to.shared.u64 t, %1; cvt.u32.u64 %0, t; }" : "=r"(a) : "l"(p));
    return a;
}
__device__ __forceinline__ void cp_async16(uint32_t saddr, const void* gptr, bool pred) {
    const int sz = pred ? 16 : 0;
    asm volatile("cp.async.cg.shared.global [%0], [%1], 16, %2;"
                 :: "r"(saddr), "l"(gptr), "r"(sz));
}
__device__ __forceinline__ void cp_commit() { asm volatile("cp.async.commit_group;"); }
template <int N>
__device__ __forceinline__ void cp_wait() { asm volatile("cp.async.wait_group %0;" :: "n"(N)); }

__device__ __forceinline__ void ldsm_x4(uint32_t* r, uint32_t a) {
    asm volatile("ldmatrix.sync.aligned.m8n8.x4.shared.b16 {%0,%1,%2,%3}, [%4];"
                 : "=r"(r[0]), "=r"(r[1]), "=r"(r[2]), "=r"(r[3]) : "r"(a));
}
__device__ __forceinline__ void ldsm_x4t(uint32_t* r, uint32_t a) {
    asm volatile("ldmatrix.sync.aligned.m8n8.x4.trans.shared.b16 {%0,%1,%2,%3}, [%4];"
                 : "=r"(r[0]), "=r"(r[1]), "=r"(r[2]), "=r"(r[3]) : "r"(a));
}
__device__ __forceinline__ void mma_fp16(float* c, const uint32_t* a, const uint32_t* b) {
    asm volatile("mma.sync.aligned.m16n8k16.row.col.f32.f16.f16.f32 "
                 "{%0,%1,%2,%3}, {%4,%5,%6,%7}, {%8,%9}, {%0,%1,%2,%3};"
                 : "+f"(c[0]), "+f"(c[1]), "+f"(c[2]), "+f"(c[3])
                 : "r"(a[0]), "r"(a[1]), "r"(a[2]), "r"(a[3]), "r"(b[0]), "r"(b[1]));
}
__device__ __forceinline__ uint32_t uh16(__half h) { return (uint32_t)__half_as_ushort(h); }

__device__ __forceinline__ uint32_t a_addr(uint32_t base, int row0, int k0, int lane, int pitch) {
    const int row = row0 + (lane & 15);
    const int col = k0 + ((lane >> 4) << 3);
    return base + (uint32_t)((row * pitch + col) * 2);
}
__device__ __forceinline__ uint32_t b_addr(uint32_t base, int n0, int k0, int lane, int pitch) {
    const int row = n0 + (lane & 7) + ((lane >> 4) << 3);
    const int col = k0 + (lane & 8);
    return base + (uint32_t)((row * pitch + col) * 2);
}

__device__ __forceinline__ uint32_t sw64(int row, int chunk) {
    return (uint32_t)((row << 6) + (((chunk ^ (row >> 1)) & 3) << 4));
}

// ---------------------------------------------------------------------------
// Merged setup: all 9 fp32 arrays -> fp16 (hi only). ONE launch.
// ---------------------------------------------------------------------------
__global__ void __launch_bounds__(256)
split_all(const float4* __restrict__ Wq, const float4* __restrict__ Wk,
          const float4* __restrict__ Wv, const float4* __restrict__ Wp,
          const float4* __restrict__ Wo,
          const float4* __restrict__ q, const float4* __restrict__ k,
          const float4* __restrict__ v, const float4* __restrict__ p)
{
    const int bid = blockIdx.x;
    const float4* src;
    __half* dst;
    int i, n4;
    if (bid < 5120) {
        const int w = bid >> 10;
        src = (w == 0) ? Wq : (w == 1) ? Wk : (w == 2) ? Wv : (w == 3) ? Wp : Wo;
        dst = g_w16 + w * 1048576;
        i = (bid & 1023) * 256 + threadIdx.x; n4 = 262144;
    } else if (bid < 9216) {
        src = q; dst = g_i16 + OIQ;
        i = (bid - 5120) * 256 + threadIdx.x; n4 = 1048576;
    } else if (bid < 13312) {
        src = k; dst = g_i16 + OIK;
        i = (bid - 9216) * 256 + threadIdx.x; n4 = 1048576;
    } else if (bid < 17408) {
        src = v; dst = g_i16 + OIV;
        i = (bid - 13312) * 256 + threadIdx.x; n4 = 1048576;
    } else {
        src = p; dst = g_i16 + OIP;
        i = (bid - 17408) * 256 + threadIdx.x; n4 = 524032;
    }
    if (i >= n4) return;
    const float4 val = src[i];
    const uint32_t h0 = uh16(__float2half_rn(val.x)), h1 = uh16(__float2half_rn(val.y));
    const uint32_t h2 = uh16(__float2half_rn(val.z)), h3 = uh16(__float2half_rn(val.w));
    uint2 H; H.x = (h1 << 16) | h0; H.y = (h3 << 16) | h2;
    ((uint2*)dst)[i] = H;
}

// ---------------------------------------------------------------------------
// fp16 hi-only GEMM core: C = A @ B^T (1 MMA/product).
// CTA 128x128, 8 warps (2x4), warp 64x32. 3-stage pipeline, swizzled smem.
// Stage = A(8K) + B(8K) = 16 KB; 3 stages = 48 KB.
// ---------------------------------------------------------------------------
#define FTS 8192
#define FSTG 16384
#define FSM_BYTES 49152

__device__ __forceinline__ void gemm_core_h(
    const __half* __restrict__ Ah, const __half* __restrict__ Bh,
    int m0, int n0, int M, char* smc, float acc[4][4][4])
{
    const uint32_t sb = smem_u32(smc);
    const int tid = threadIdx.x;
    const int lane = tid & 31;
    const int wid = tid >> 5;
    const int wm = wid >> 2, wn = wid & 3;

    const __half* gsrc[4];
    uint32_t soff[4];
    #pragma unroll
    for (int j = 0; j < 4; j++) {
        const int f = tid + 256 * j;
        const int tile = f >> 9;             // 0=A, 1=B
        const int idx = f & 511;
        const int row = idx >> 2;
        const int ch = idx & 3;
        int r = ((tile == 0) ? m0 : n0) + row;
        if (tile == 0 && r > M - 1) r = M - 1;
        gsrc[j] = ((tile == 0) ? Ah : Bh) + (size_t)r * C_DIM + ch * 8;
        soff[j] = (uint32_t)(tile * FTS) + sw64(row, ch);
    }

    #pragma unroll
    for (int j = 0; j < 4; j++) cp_async16(sb + soff[j], gsrc[j], true);
    cp_commit();
    #pragma unroll
    for (int j = 0; j < 4; j++) cp_async16(sb + FSTG + soff[j], gsrc[j] + 32, true);
    cp_commit();

    int stage = 0;
    for (int kc = 0; kc < 32; kc++) {
        if (kc < 31) cp_wait<1>(); else cp_wait<0>();
        __syncthreads();
        if (kc + 2 < 32) {
            const int pst = (stage + 2 >= 3) ? stage - 1 : stage + 2;
            const uint32_t pb = sb + (uint32_t)pst * FSTG;
            const int kof = (kc + 2) * 32;
            #pragma unroll
            for (int j = 0; j < 4; j++)
                cp_async16(pb + soff[j], gsrc[j] + kof, true);
            cp_commit();
        }
        const uint32_t sab = sb + (uint32_t)stage * FSTG;
        #pragma unroll
        for (int ks = 0; ks < 2; ks++) {
            const int c0 = ks * 2;
            uint32_t bh[2][4];
            #pragma unroll
            for (int p = 0; p < 2; p++) {
                const int brow = wn * 32 + p * 16 + (lane & 7) + ((lane >> 4) << 3);
                const int bch = c0 + ((lane >> 3) & 1);
                ldsm_x4(bh[p], sab + FTS + sw64(brow, bch));
            }
            #pragma unroll
            for (int mt = 0; mt < 4; mt++) {
                const int arow = wm * 64 + mt * 16 + (lane & 15);
                const int ach = c0 + (lane >> 4);
                uint32_t ah[4];
                ldsm_x4(ah, sab + sw64(arow, ach));
                #pragma unroll
                for (int nt = 0; nt < 4; nt++)
                    mma_fp16(acc[mt][nt], ah, &bh[nt >> 1][(nt & 1) * 2]);
            }
        }
        stage = (stage + 1 >= 3) ? 0 : stage + 1;
    }
}

// ---------------------------------------------------------------------------
// Mega projection: q,k,v,p in one launch (896 CTAs, tile 128x128), all hi-only.
// ---------------------------------------------------------------------------
__global__ void __launch_bounds__(256, 2)
proj_mega(const float* __restrict__ bq, const float* __restrict__ bk,
          const float* __restrict__ bv, const float* __restrict__ pbu)
{
    extern __shared__ char smc[];
    const int id = blockIdx.x;
    int op, mi, ni;
    if (id < 768) { op = id >> 8; const int r = id & 255; mi = r >> 3; ni = r & 7; }
    else          { op = 3; const int r = id - 768; mi = r >> 3; ni = r & 7; }

    const int inoff = (op == 0) ? OIQ : (op == 1) ? OIK : (op == 2) ? OIV : OIP;
    const int woff  = op * 1048576;
    const int M = (op == 3) ? P_DIM : BT_DIM;
    const int m0 = mi * 128, n0 = ni * 128;

    float acc[4][4][4] = {};
    gemm_core_h(g_i16 + inoff, g_w16 + woff, m0, n0, M, smc, acc);

    const int lane = threadIdx.x & 31, wid = threadIdx.x >> 5;
    const int g = lane >> 2, tg = lane & 3, wm = wid >> 2, wn = wid & 3;
    __half* gh = (op == 0) ? g_qu16 : (op == 1) ? g_k16 : (op == 2) ? g_v16 : g_p16;

    #pragma unroll
    for (int mt = 0; mt < 4; mt++) {
        const int r0 = m0 + wm * 64 + mt * 16 + g;
        const int r1 = r0 + 8;
        #pragma unroll
        for (int nt = 0; nt < 4; nt++) {
            const int col = n0 + wn * 32 + nt * 8 + 2 * tg;
            float b0 = 0.f, b1 = 0.f;
            if (op == 0)      { b0 = bq[col] + pbu[col]; b1 = bq[col + 1] + pbu[col + 1]; }
            else if (op == 1) { b0 = bk[col]; b1 = bk[col + 1]; }
            else if (op == 2) { b0 = bv[col]; b1 = bv[col + 1]; }
            float x0 = acc[mt][nt][0] + b0, x1 = acc[mt][nt][1] + b1;
            float x2 = acc[mt][nt][2] + b0, x3 = acc[mt][nt][3] + b1;
            if (op == 0) { x0 *= 0.125f; x1 *= 0.125f; x2 *= 0.125f; x3 *= 0.125f; }
            if (r0 < M)
                *(__half2*)(gh + (size_t)r0 * C_DIM + col) =
                    __halves2half2(__float2half_rn(x0), __float2half_rn(x1));
            if (r1 < M)
                *(__half2*)(gh + (size_t)r1 * C_DIM + col) =
                    __halves2half2(__float2half_rn(x2), __float2half_rn(x3));
        }
    }
}

// Output projection: A = attention out (fp16), writes fp32 d_out.
__global__ void __launch_bounds__(256, 2)
gemm_out(const float* __restrict__ bias, float* __restrict__ Cout)
{
    extern __shared__ char smc[];
    const int mi = blockIdx.x >> 3, ni = blockIdx.x & 7;
    const int m0 = mi * 128, n0 = ni * 128;
    float acc[4][4][4] = {};
    gemm_core_h(g_x16, g_w16 + OWO, m0, n0, BT_DIM, smc, acc);

    const int lane = threadIdx.x & 31, wid = threadIdx.x >> 5;
    const int g = lane >> 2, tg = lane & 3, wm = wid >> 2, wn = wid & 3;
    #pragma unroll
    for (int mt = 0; mt < 4; mt++) {
        const int r0 = m0 + wm * 64 + mt * 16 + g;
        #pragma unroll
        for (int nt = 0; nt < 4; nt++) {
            const int col = n0 + wn * 32 + nt * 8 + 2 * tg;
            const float b0 = bias[col], b1 = bias[col + 1];
            *(float2*)(Cout + (size_t)r0 * C_DIM + col) =
                make_float2(acc[mt][nt][0] + b0, acc[mt][nt][1] + b1);
            *(float2*)(Cout + (size_t)(r0 + 8) * C_DIM + col) =
                make_float2(acc[mt][nt][2] + b0, acc[mt][nt][3] + b1);
        }
    }
}

// ---------------------------------------------------------------------------
// Attention (fp16 hi-only everywhere): AC/G/PV all 1 MMA per product.
// Smem 65280 B -> up to 3 CTAs/SM. R15 choreography otherwise unchanged.
// NOTE: BD fp32 staging (64x68 f32 = 17408 B) lives in the 18432-B P region
// and aliases the P fp16 tile ACROSS WARPS — the barrier between exp (BD
// reads) and P stores is mandatory.
// ---------------------------------------------------------------------------
#define ATP 72
#define OQU 0
#define OKH 9216
#define OVH 18432
#define OBH 27648
#define OPH 46080
#define OEV 64512
#define ODL 65024
#define ATT_BYTES 65280

__global__ void __launch_bounds__(128)
attn_f16(const float* __restrict__ pbu, const float* __restrict__ pbv)
{
    extern __shared__ char smc[];
    const uint32_t sb = smem_u32(smc);
    const int tid = threadIdx.x;
    const int wid = tid >> 5;
    const int lane = tid & 31;
    const int g = lane >> 2, tg = lane & 3;
    const int t0 = blockIdx.x * 64;
    const int b = (int)blockIdx.y >> 4;
    const int h = (int)blockIdx.y & 15;
    const int row0w = wid * 16;
    const int row0g = row0w + g;
    const int cbase = 48 - row0w;

    // Prologue: G1 = K0 + band0, G2 = QU, G3 = V0
    {
        const int w0 = 960 - t0;
        #pragma unroll
        for (int jj = 0; jj < 4; jj++) {
            const int f = tid + 128 * jj;
            const int row = f >> 3, ch = f & 7;
            cp_async16(sb + OKH + (uint32_t)((row * ATP + ch * 8) * 2),
                       g_k16 + ((size_t)row * B_DIM + b) * C_DIM + h * 64 + ch * 8, true);
        }
        #pragma unroll
        for (int jj = 0; jj < 8; jj++) {
            const int f = tid + 128 * jj;
            const int row = f >> 3, ch = f & 7;
            if (row < 127) {
                const int pr = w0 + row;
                const int slot = pr & 127;
                cp_async16(sb + OBH + (uint32_t)((slot * ATP + ch * 8) * 2),
                           g_p16 + (size_t)pr * C_DIM + h * 64 + ch * 8, true);
            }
        }
        cp_commit();
        #pragma unroll
        for (int jj = 0; jj < 4; jj++) {
            const int f = tid + 128 * jj;
            const int row = f >> 3, ch = f & 7;
            cp_async16(sb + OQU + (uint32_t)((row * ATP + ch * 8) * 2),
                       g_qu16 + ((size_t)(t0 + row) * B_DIM + b) * C_DIM + h * 64 + ch * 8, true);
        }
        cp_commit();
        #pragma unroll
        for (int jj = 0; jj < 4; jj++) {
            const int f = tid + 128 * jj;
            const int row = f >> 3, ch = f & 7;
            cp_async16(sb + OVH + (uint32_t)((row * ATP + ch * 8) * 2),
                       g_v16 + ((size_t)row * B_DIM + b) * C_DIM + h * 64 + ch * 8, true);
        }
        cp_commit();
    }

    if (tid < 64)
        ((float*)(smc + ODL))[tid] = (pbv[h * 64 + tid] - pbu[h * 64 + tid]) * 0.125f;

    cp_wait<1>();
    __syncthreads();

    // Loop-invariant QU fragments
    uint32_t qu[4][4];
    #pragma unroll
    for (int k = 0; k < 4; k++)
        ldsm_x4(qu[k], a_addr(sb + OQU, row0w, k * 16, lane, ATP));

    float oacc[8][4];
    #pragma unroll
    for (int nt = 0; nt < 8; nt++)
        #pragma unroll
        for (int r = 0; r < 4; r++) oacc[nt][r] = 0.f;
    float lp0 = 0.f, lp1 = 0.f;

    for (int it = 0; it < 16; it++) {
        const int s0 = it * 64;
        const int off = (s0 - t0 + 960) & 127;
        const int s0n = (s0 + 64 < T_DIM) ? s0 + 64 : s0;
        const int wnx = s0n - t0 + 960;

        cp_wait<1>();
        __syncthreads();

        // e[c] = delta . band[c]
        if (tid < 127) {
            const int phys = (off + tid) & 127;
            const __half2* bh2 = (const __half2*)((__half*)(smc + OBH) + phys * ATP);
            const float2* dl2 = (const float2*)(smc + ODL);
            float s = 0.f;
            #pragma unroll
            for (int d2 = 0; d2 < 32; d2++) {
                const __half2 hh = bh2[d2];
                const float2 dv = dl2[d2];
                s = fmaf(__half2float(hh.x), dv.x, fmaf(__half2float(hh.y), dv.y, s));
            }
            ((float*)(smc + OEV))[tid] = s;
        }

        // Stage 1: AC = Qu @ K^T (1 MMA/product)
        float sacc[8][4];
        #pragma unroll
        for (int nt = 0; nt < 8; nt++)
            #pragma unroll
            for (int r = 0; r < 4; r++) sacc[nt][r] = 0.f;
        #pragma unroll
        for (int k = 0; k < 4; k++) {
            #pragma unroll
            for (int p = 0; p < 4; p++) {
                uint32_t kh4[4];
                ldsm_x4(kh4, b_addr(sb + OKH, p * 16, k * 16, lane, ATP));
                mma_fp16(sacc[2 * p],     qu[k], kh4);
                mma_fp16(sacc[2 * p + 1], qu[k], kh4 + 2);
            }
        }
        __syncthreads();   // K reads done; EV visible

        // prefetch K_{i+1}
        #pragma unroll
        for (int jj = 0; jj < 4; jj++) {
            const int f = tid + 128 * jj;
            const int row = f >> 3, ch = f & 7;
            cp_async16(sb + OKH + (uint32_t)((row * ATP + ch * 8) * 2),
                       g_k16 + ((size_t)(s0n + row) * B_DIM + b) * C_DIM + h * 64 + ch * 8, true);
        }
        cp_commit();

        // Stage 2: windowed G = Qu @ band^T (5 p-tiles, 1 MMA/product)
        float gacc[10][4];
        #pragma unroll
        for (int nt = 0; nt < 10; nt++)
            #pragma unroll
            for (int r = 0; r < 4; r++) gacc[nt][r] = 0.f;
        #pragma unroll
        for (int k = 0; k < 4; k++) {
            #pragma unroll
            for (int p = 0; p < 5; p++) {
                const int basep = (off + cbase + p * 16) & 127;
                uint32_t bh4[4];
                ldsm_x4(bh4, b_addr(sb + OBH, basep, k * 16, lane, ATP));
                mma_fp16(gacc[2 * p],     qu[k], bh4);
                mma_fp16(gacc[2 * p + 1], qu[k], bh4 + 2);
            }
        }
        {
            float* BD = (float*)(smc + OPH);
            const float* EV = (const float*)(smc + OEV);
            #pragma unroll
            for (int nt = 0; nt < 10; nt++)
                #pragma unroll
                for (int r2 = 0; r2 < 2; r2++) {
                    const int t = row0g + 8 * r2;
                    #pragma unroll
                    for (int cc = 0; cc < 2; cc++) {
                        const int c = cbase + nt * 8 + 2 * tg + cc;
                        const int s = c - 63 + t;
                        if (s >= 0 && s < 64)
                            BD[t * 68 + s] = gacc[nt][r2 * 2 + cc] + EV[c];
                    }
                }
        }
        __syncthreads();   // band reads done (before band prefetch); BD visible

        // prefetch band_{i+1}: 64 new p-rows
        #pragma unroll
        for (int jj = 0; jj < 4; jj++) {
            const int f = tid + 128 * jj;
            const int row = f >> 3, ch = f & 7;
            const int pr = wnx + 63 + row;
            const int slot = pr & 127;
            cp_async16(sb + OBH + (uint32_t)((slot * ATP + ch * 8) * 2),
                       g_p16 + (size_t)pr * C_DIM + h * 64 + ch * 8, true);
        }
        cp_commit();

        // Stage 3: P = exp(ac + bd)
        const float* BD = (const float*)(smc + OPH);
        float pval[8][4];
        #pragma unroll
        for (int nt = 0; nt < 8; nt++)
            #pragma unroll
            for (int r2 = 0; r2 < 2; r2++) {
                const int t = row0g + 8 * r2;
                #pragma unroll
                for (int cc = 0; cc < 2; cc++) {
                    const int s = nt * 8 + 2 * tg + cc;
                    float v = sacc[nt][r2 * 2 + cc] + BD[t * 68 + s];
                    v = __expf(fminf(v, 10.f));
                    pval[nt][r2 * 2 + cc] = v;
                    if (r2 == 0) lp0 += v; else lp1 += v;
                }
            }
        __syncthreads();   // MANDATORY: BD aliases the P tile across warps
        {
            __half* Ph = (__half*)(smc + OPH);
            #pragma unroll
            for (int nt = 0; nt < 8; nt++)
                #pragma unroll
                for (int r2 = 0; r2 < 2; r2++) {
                    const int t = row0g + 8 * r2;
                    const int s = nt * 8 + 2 * tg;
                    *(__half2*)(Ph + (size_t)(t * ATP + s)) =
                        __halves2half2(__float2half_rn(pval[nt][r2 * 2]),
                                       __float2half_rn(pval[nt][r2 * 2 + 1]));
                }
        }
        cp_wait<2>();      // V_i arrived
        __syncthreads();   // P + V visible

        // Stage 4: O += P @ V (1 MMA/product)
        #pragma unroll
        for (int k = 0; k < 4; k++) {
            uint32_t aph[4];
            ldsm_x4(aph, a_addr(sb + OPH, row0w, k * 16, lane, ATP));
            #pragma unroll
            for (int p = 0; p < 4; p++) {
                uint32_t vh4[4];
                ldsm_x4t(vh4, a_addr(sb + OVH, k * 16, p * 16, lane, ATP));
                mma_fp16(oacc[2 * p],     aph, vh4);
                mma_fp16(oacc[2 * p + 1], aph, vh4 + 2);
            }
        }
        __syncthreads();   // V reads done

        // prefetch V_{i+1}
        #pragma unroll
        for (int jj = 0; jj < 4; jj++) {
            const int f = tid + 128 * jj;
            const int row = f >> 3, ch = f & 7;
            cp_async16(sb + OVH + (uint32_t)((row * ATP + ch * 8) * 2),
                       g_v16 + ((size_t)(s0n + row) * B_DIM + b) * C_DIM + h * 64 + ch * 8, true);
        }
        cp_commit();
    }
    cp_wait<0>();

    lp0 += __shfl_xor_sync(0xffffffffu, lp0, 1);
    lp0 += __shfl_xor_sync(0xffffffffu, lp0, 2);
    lp1 += __shfl_xor_sync(0xffffffffu, lp1, 1);
    lp1 += __shfl_xor_sync(0xffffffffu, lp1, 2);
    const float inv0 = 1.f / lp0;
    const float inv1 = 1.f / lp1;

    #pragma unroll
    for (int nt = 0; nt < 8; nt++) {
        const int col = h * 64 + nt * 8 + 2 * tg;
        const size_t o0 = ((size_t)(t0 + row0g) * B_DIM + b) * C_DIM + col;
        const size_t o1 = ((size_t)(t0 + row0g + 8) * B_DIM + b) * C_DIM + col;
        *(__half2*)(g_x16 + o0) =
            __halves2half2(__float2half_rn(oacc[nt][0] * inv0),
                           __float2half_rn(oacc[nt][1] * inv0));
        *(__half2*)(g_x16 + o1) =
            __halves2half2(__float2half_rn(oacc[nt][2] * inv1),
                           __float2half_rn(oacc[nt][3] * inv1));
    }
}

// ---------------------------------------------------------------------------
// Launch
// ---------------------------------------------------------------------------
extern "C" void kernel_launch(void* const* d_in, const int* in_sizes, int n_in,
                              void* d_out, int out_size)
{
    const float* query   = (const float*)d_in[0];
    const float* key     = (const float*)d_in[1];
    const float* value   = (const float*)d_in[2];
    const float* pos_emb = (const float*)d_in[3];
    const float* Wq      = (const float*)d_in[4];
    const float* bq      = (const float*)d_in[5];
    const float* Wk      = (const float*)d_in[6];
    const float* bk      = (const float*)d_in[7];
    const float* Wv      = (const float*)d_in[8];
    const float* bv      = (const float*)d_in[9];
    const float* Wp      = (const float*)d_in[10];
    const float* Wo      = (const float*)d_in[11];
    const float* bo      = (const float*)d_in[12];
    const float* pbu     = (const float*)d_in[13];
    const float* pbv     = (const float*)d_in[14];
    float* out = (float*)d_out;

    cudaFuncSetAttribute(proj_mega, cudaFuncAttributeMaxDynamicSharedMemorySize, FSM_BYTES);
    cudaFuncSetAttribute(gemm_out,  cudaFuncAttributeMaxDynamicSharedMemorySize, FSM_BYTES);
    cudaFuncSetAttribute(attn_f16,  cudaFuncAttributeMaxDynamicSharedMemorySize, ATT_BYTES);

    split_all<<<19455, 256>>>((const float4*)Wq, (const float4*)Wk, (const float4*)Wv,
                              (const float4*)Wp, (const float4*)Wo,
                              (const float4*)query, (const float4*)key,
                              (const float4*)value, (const float4*)pos_emb);

    proj_mega<<<896, 256, FSM_BYTES>>>(bq, bk, bv, pbu);
    attn_f16<<<dim3(16, 64), 128, ATT_BYTES>>>(pbu, pbv);
    gemm_out<<<256, 256, FSM_BYTES>>>(bo, out);
}

// round 17
// speedup vs baseline: 2.2972x; 1.0498x over previous
#include <cuda_runtime.h>
#include <cuda_fp16.h>
#include <math_constants.h>
#include <cstdint>

// Problem constants
#define T_DIM 1024
#define B_DIM 4
#define C_DIM 1024
#define H_DIM 16
#define D_DIM 64
#define P_DIM 2047
#define BT_DIM (B_DIM * T_DIM)
#define LOG2E 1.4426950408889634f

// Scratch (device globals). Row order m = t*B + b ([T,B,C] natural).
__device__ __half g_qu16[BT_DIM * C_DIM];    // (q@Wq+bq+pbu)*0.125*log2e, fp16
__device__ __half g_k16[BT_DIM * C_DIM];
__device__ __half g_v16[BT_DIM * C_DIM];
__device__ __half g_p16[P_DIM * C_DIM];
__device__ __half g_x16[BT_DIM * C_DIM];     // attention out, fp16
#define OWQ 0
#define OWK 1048576
#define OWV 2097152
#define OWP 3145728
#define OWO 4194304
__device__ __half g_w16[5 * 1048576];        // weights, fp16
#define OIQ 0
#define OIK 4194304
#define OIV 8388608
#define OIP 12582912
__device__ __half g_i16[14679040];           // inputs, fp16

// ---------------------------------------------------------------------------
// Helpers
// ---------------------------------------------------------------------------
__device__ __forceinline__ uint32_t smem_u32(const void* p) {
    uint32_t a;
    asm("{ .reg .u64 t; cvta.to.shared.u64 t, %1; cvt.u32.u64 %0, t; }" : "=r"(a) : "l"(p));
    return a;
}
__device__ __forceinline__ void cp_async16(uint32_t saddr, const void* gptr, bool pred) {
    const int sz = pred ? 16 : 0;
    asm volatile("cp.async.cg.shared.global [%0], [%1], 16, %2;"
                 :: "r"(saddr), "l"(gptr), "r"(sz));
}
__device__ __forceinline__ void cp_commit() { asm volatile("cp.async.commit_group;"); }
template <int N>
__device__ __forceinline__ void cp_wait() { asm volatile("cp.async.wait_group %0;" :: "n"(N)); }

__device__ __forceinline__ void ldsm_x4(uint32_t* r, uint32_t a) {
    asm volatile("ldmatrix.sync.aligned.m8n8.x4.shared.b16 {%0,%1,%2,%3}, [%4];"
                 : "=r"(r[0]), "=r"(r[1]), "=r"(r[2]), "=r"(r[3]) : "r"(a));
}
__device__ __forceinline__ void ldsm_x4t(uint32_t* r, uint32_t a) {
    asm volatile("ldmatrix.sync.aligned.m8n8.x4.trans.shared.b16 {%0,%1,%2,%3}, [%4];"
                 : "=r"(r[0]), "=r"(r[1]), "=r"(r[2]), "=r"(r[3]) : "r"(a));
}
__device__ __forceinline__ void mma_fp16(float* c, const uint32_t* a, const uint32_t* b) {
    asm volatile("mma.sync.aligned.m16n8k16.row.col.f32.f16.f16.f32 "
                 "{%0,%1,%2,%3}, {%4,%5,%6,%7}, {%8,%9}, {%0,%1,%2,%3};"
                 : "+f"(c[0]), "+f"(c[1]), "+f"(c[2]), "+f"(c[3])
                 : "r"(a[0]), "r"(a[1]), "r"(a[2]), "r"(a[3]), "r"(b[0]), "r"(b[1]));
}
__device__ __forceinline__ uint32_t uh16(__half h) { return (uint32_t)__half_as_ushort(h); }

__device__ __forceinline__ uint32_t a_addr(uint32_t base, int row0, int k0, int lane, int pitch) {
    const int row = row0 + (lane & 15);
    const int col = k0 + ((lane >> 4) << 3);
    return base + (uint32_t)((row * pitch + col) * 2);
}
__device__ __forceinline__ uint32_t b_addr(uint32_t base, int n0, int k0, int lane, int pitch) {
    const int row = n0 + (lane & 7) + ((lane >> 4) << 3);
    const int col = k0 + (lane & 8);
    return base + (uint32_t)((row * pitch + col) * 2);
}

__device__ __forceinline__ uint32_t sw64(int row, int chunk) {
    return (uint32_t)((row << 6) + (((chunk ^ (row >> 1)) & 3) << 4));
}

// ---------------------------------------------------------------------------
// Merged setup: all 9 fp32 arrays -> fp16 (hi only). ONE launch.
// ---------------------------------------------------------------------------
__global__ void __launch_bounds__(256)
split_all(const float4* __restrict__ Wq, const float4* __restrict__ Wk,
          const float4* __restrict__ Wv, const float4* __restrict__ Wp,
          const float4* __restrict__ Wo,
          const float4* __restrict__ q, const float4* __restrict__ k,
          const float4* __restrict__ v, const float4* __restrict__ p)
{
    const int bid = blockIdx.x;
    const float4* src;
    __half* dst;
    int i, n4;
    if (bid < 5120) {
        const int w = bid >> 10;
        src = (w == 0) ? Wq : (w == 1) ? Wk : (w == 2) ? Wv : (w == 3) ? Wp : Wo;
        dst = g_w16 + w * 1048576;
        i = (bid & 1023) * 256 + threadIdx.x; n4 = 262144;
    } else if (bid < 9216) {
        src = q; dst = g_i16 + OIQ;
        i = (bid - 5120) * 256 + threadIdx.x; n4 = 1048576;
    } else if (bid < 13312) {
        src = k; dst = g_i16 + OIK;
        i = (bid - 9216) * 256 + threadIdx.x; n4 = 1048576;
    } else if (bid < 17408) {
        src = v; dst = g_i16 + OIV;
        i = (bid - 13312) * 256 + threadIdx.x; n4 = 1048576;
    } else {
        src = p; dst = g_i16 + OIP;
        i = (bid - 17408) * 256 + threadIdx.x; n4 = 524032;
    }
    if (i >= n4) return;
    const float4 val = src[i];
    const uint32_t h0 = uh16(__float2half_rn(val.x)), h1 = uh16(__float2half_rn(val.y));
    const uint32_t h2 = uh16(__float2half_rn(val.z)), h3 = uh16(__float2half_rn(val.w));
    uint2 H; H.x = (h1 << 16) | h0; H.y = (h3 << 16) | h2;
    ((uint2*)dst)[i] = H;
}

// ---------------------------------------------------------------------------
// fp16 hi-only GEMM core: C = A @ B^T (1 MMA/product).
// CTA 128x128, 8 warps (2x4), warp 64x32. 3-stage pipeline, swizzled smem.
// ---------------------------------------------------------------------------
#define FTS 8192
#define FSTG 16384
#define FSM_BYTES 49152

__device__ __forceinline__ void gemm_core_h(
    const __half* __restrict__ Ah, const __half* __restrict__ Bh,
    int m0, int n0, int M, char* smc, float acc[4][4][4])
{
    const uint32_t sb = smem_u32(smc);
    const int tid = threadIdx.x;
    const int lane = tid & 31;
    const int wid = tid >> 5;
    const int wm = wid >> 2, wn = wid & 3;

    const __half* gsrc[4];
    uint32_t soff[4];
    #pragma unroll
    for (int j = 0; j < 4; j++) {
        const int f = tid + 256 * j;
        const int tile = f >> 9;
        const int idx = f & 511;
        const int row = idx >> 2;
        const int ch = idx & 3;
        int r = ((tile == 0) ? m0 : n0) + row;
        if (tile == 0 && r > M - 1) r = M - 1;
        gsrc[j] = ((tile == 0) ? Ah : Bh) + (size_t)r * C_DIM + ch * 8;
        soff[j] = (uint32_t)(tile * FTS) + sw64(row, ch);
    }

    #pragma unroll
    for (int j = 0; j < 4; j++) cp_async16(sb + soff[j], gsrc[j], true);
    cp_commit();
    #pragma unroll
    for (int j = 0; j < 4; j++) cp_async16(sb + FSTG + soff[j], gsrc[j] + 32, true);
    cp_commit();

    int stage = 0;
    for (int kc = 0; kc < 32; kc++) {
        if (kc < 31) cp_wait<1>(); else cp_wait<0>();
        __syncthreads();
        if (kc + 2 < 32) {
            const int pst = (stage + 2 >= 3) ? stage - 1 : stage + 2;
            const uint32_t pb = sb + (uint32_t)pst * FSTG;
            const int kof = (kc + 2) * 32;
            #pragma unroll
            for (int j = 0; j < 4; j++)
                cp_async16(pb + soff[j], gsrc[j] + kof, true);
            cp_commit();
        }
        const uint32_t sab = sb + (uint32_t)stage * FSTG;
        #pragma unroll
        for (int ks = 0; ks < 2; ks++) {
            const int c0 = ks * 2;
            uint32_t bh[2][4];
            #pragma unroll
            for (int p = 0; p < 2; p++) {
                const int brow = wn * 32 + p * 16 + (lane & 7) + ((lane >> 4) << 3);
                const int bch = c0 + ((lane >> 3) & 1);
                ldsm_x4(bh[p], sab + FTS + sw64(brow, bch));
            }
            #pragma unroll
            for (int mt = 0; mt < 4; mt++) {
                const int arow = wm * 64 + mt * 16 + (lane & 15);
                const int ach = c0 + (lane >> 4);
                uint32_t ah[4];
                ldsm_x4(ah, sab + sw64(arow, ach));
                #pragma unroll
                for (int nt = 0; nt < 4; nt++)
                    mma_fp16(acc[mt][nt], ah, &bh[nt >> 1][(nt & 1) * 2]);
            }
        }
        stage = (stage + 1 >= 3) ? 0 : stage + 1;
    }
}

// ---------------------------------------------------------------------------
// Mega projection: q,k,v,p in one launch (896 CTAs, tile 128x128).
// op0 scale now includes log2e (scores come out in log2 domain).
// ---------------------------------------------------------------------------
__global__ void __launch_bounds__(256, 2)
proj_mega(const float* __restrict__ bq, const float* __restrict__ bk,
          const float* __restrict__ bv, const float* __restrict__ pbu)
{
    extern __shared__ char smc[];
    const int id = blockIdx.x;
    int op, mi, ni;
    if (id < 768) { op = id >> 8; const int r = id & 255; mi = r >> 3; ni = r & 7; }
    else          { op = 3; const int r = id - 768; mi = r >> 3; ni = r & 7; }

    const int inoff = (op == 0) ? OIQ : (op == 1) ? OIK : (op == 2) ? OIV : OIP;
    const int woff  = op * 1048576;
    const int M = (op == 3) ? P_DIM : BT_DIM;
    const int m0 = mi * 128, n0 = ni * 128;

    float acc[4][4][4] = {};
    gemm_core_h(g_i16 + inoff, g_w16 + woff, m0, n0, M, smc, acc);

    const int lane = threadIdx.x & 31, wid = threadIdx.x >> 5;
    const int g = lane >> 2, tg = lane & 3, wm = wid >> 2, wn = wid & 3;
    __half* gh = (op == 0) ? g_qu16 : (op == 1) ? g_k16 : (op == 2) ? g_v16 : g_p16;
    const float qscale = 0.125f * LOG2E;

    #pragma unroll
    for (int mt = 0; mt < 4; mt++) {
        const int r0 = m0 + wm * 64 + mt * 16 + g;
        const int r1 = r0 + 8;
        #pragma unroll
        for (int nt = 0; nt < 4; nt++) {
            const int col = n0 + wn * 32 + nt * 8 + 2 * tg;
            float b0 = 0.f, b1 = 0.f;
            if (op == 0)      { b0 = bq[col] + pbu[col]; b1 = bq[col + 1] + pbu[col + 1]; }
            else if (op == 1) { b0 = bk[col]; b1 = bk[col + 1]; }
            else if (op == 2) { b0 = bv[col]; b1 = bv[col + 1]; }
            float x0 = acc[mt][nt][0] + b0, x1 = acc[mt][nt][1] + b1;
            float x2 = acc[mt][nt][2] + b0, x3 = acc[mt][nt][3] + b1;
            if (op == 0) { x0 *= qscale; x1 *= qscale; x2 *= qscale; x3 *= qscale; }
            if (r0 < M)
                *(__half2*)(gh + (size_t)r0 * C_DIM + col) =
                    __halves2half2(__float2half_rn(x0), __float2half_rn(x1));
            if (r1 < M)
                *(__half2*)(gh + (size_t)r1 * C_DIM + col) =
                    __halves2half2(__float2half_rn(x2), __float2half_rn(x3));
        }
    }
}

// Output projection: A = attention out (fp16), writes fp32 d_out.
__global__ void __launch_bounds__(256, 2)
gemm_out(const float* __restrict__ bias, float* __restrict__ Cout)
{
    extern __shared__ char smc[];
    const int mi = blockIdx.x >> 3, ni = blockIdx.x & 7;
    const int m0 = mi * 128, n0 = ni * 128;
    float acc[4][4][4] = {};
    gemm_core_h(g_x16, g_w16 + OWO, m0, n0, BT_DIM, smc, acc);

    const int lane = threadIdx.x & 31, wid = threadIdx.x >> 5;
    const int g = lane >> 2, tg = lane & 3, wm = wid >> 2, wn = wid & 3;
    #pragma unroll
    for (int mt = 0; mt < 4; mt++) {
        const int r0 = m0 + wm * 64 + mt * 16 + g;
        #pragma unroll
        for (int nt = 0; nt < 4; nt++) {
            const int col = n0 + wn * 32 + nt * 8 + 2 * tg;
            const float b0 = bias[col], b1 = bias[col + 1];
            *(float2*)(Cout + (size_t)r0 * C_DIM + col) =
                make_float2(acc[mt][nt][0] + b0, acc[mt][nt][1] + b1);
            *(float2*)(Cout + (size_t)(r0 + 8) * C_DIM + col) =
                make_float2(acc[mt][nt][2] + b0, acc[mt][nt][3] + b1);
        }
    }
}

// ---------------------------------------------------------------------------
// Attention (fp16, log2-domain softmax):
//  - scores arrive x log2e (folded into QU/delta scales)
//  - exp via cvt.rn.f16x2.f32 + ex2.approx.f16x2 (2 at a time, output IS fp16 P)
//  - row sums via ones-B MMA (l = P @ 1) in Stage 4 -> no fp32 adds, no shuffles
// R16 choreography otherwise unchanged. BD fp32 staging aliases the P tile
// ACROSS WARPS -> barrier between exp (BD reads) and P stores is mandatory.
// ---------------------------------------------------------------------------
#define ATP 72
#define OQU 0
#define OKH 9216
#define OVH 18432
#define OBH 27648
#define OPH 46080
#define OEV 64512
#define ODL 65024
#define ATT_BYTES 65280

__global__ void __launch_bounds__(128)
attn_f16(const float* __restrict__ pbu, const float* __restrict__ pbv)
{
    extern __shared__ char smc[];
    const uint32_t sb = smem_u32(smc);
    const int tid = threadIdx.x;
    const int wid = tid >> 5;
    const int lane = tid & 31;
    const int g = lane >> 2, tg = lane & 3;
    const int t0 = blockIdx.x * 64;
    const int b = (int)blockIdx.y >> 4;
    const int h = (int)blockIdx.y & 15;
    const int row0w = wid * 16;
    const int row0g = row0w + g;
    const int cbase = 48 - row0w;

    // Prologue: G1 = K0 + band0, G2 = QU, G3 = V0
    {
        const int w0 = 960 - t0;
        #pragma unroll
        for (int jj = 0; jj < 4; jj++) {
            const int f = tid + 128 * jj;
            const int row = f >> 3, ch = f & 7;
            cp_async16(sb + OKH + (uint32_t)((row * ATP + ch * 8) * 2),
                       g_k16 + ((size_t)row * B_DIM + b) * C_DIM + h * 64 + ch * 8, true);
        }
        #pragma unroll
        for (int jj = 0; jj < 8; jj++) {
            const int f = tid + 128 * jj;
            const int row = f >> 3, ch = f & 7;
            if (row < 127) {
                const int pr = w0 + row;
                const int slot = pr & 127;
                cp_async16(sb + OBH + (uint32_t)((slot * ATP + ch * 8) * 2),
                           g_p16 + (size_t)pr * C_DIM + h * 64 + ch * 8, true);
            }
        }
        cp_commit();
        #pragma unroll
        for (int jj = 0; jj < 4; jj++) {
            const int f = tid + 128 * jj;
            const int row = f >> 3, ch = f & 7;
            cp_async16(sb + OQU + (uint32_t)((row * ATP + ch * 8) * 2),
                       g_qu16 + ((size_t)(t0 + row) * B_DIM + b) * C_DIM + h * 64 + ch * 8, true);
        }
        cp_commit();
        #pragma unroll
        for (int jj = 0; jj < 4; jj++) {
            const int f = tid + 128 * jj;
            const int row = f >> 3, ch = f & 7;
            cp_async16(sb + OVH + (uint32_t)((row * ATP + ch * 8) * 2),
                       g_v16 + ((size_t)row * B_DIM + b) * C_DIM + h * 64 + ch * 8, true);
        }
        cp_commit();
    }

    if (tid < 64)
        ((float*)(smc + ODL))[tid] = (pbv[h * 64 + tid] - pbu[h * 64 + tid]) * (0.125f * LOG2E);

    cp_wait<1>();
    __syncthreads();

    // Loop-invariant QU fragments
    uint32_t qu[4][4];
    #pragma unroll
    for (int k = 0; k < 4; k++)
        ldsm_x4(qu[k], a_addr(sb + OQU, row0w, k * 16, lane, ATP));

    // all-ones B fragment for row-sum MMA (1.0 in fp16 = 0x3C00)
    const uint32_t bones[2] = {0x3C003C00u, 0x3C003C00u};

    float oacc[8][4];
    #pragma unroll
    for (int nt = 0; nt < 8; nt++)
        #pragma unroll
        for (int r = 0; r < 4; r++) oacc[nt][r] = 0.f;
    float lacc[4] = {0.f, 0.f, 0.f, 0.f};

    for (int it = 0; it < 16; it++) {
        const int s0 = it * 64;
        const int off = (s0 - t0 + 960) & 127;
        const int s0n = (s0 + 64 < T_DIM) ? s0 + 64 : s0;
        const int wnx = s0n - t0 + 960;

        cp_wait<1>();
        __syncthreads();

        // e[c] = delta . band[c]
        if (tid < 127) {
            const int phys = (off + tid) & 127;
            const __half2* bh2 = (const __half2*)((__half*)(smc + OBH) + phys * ATP);
            const float2* dl2 = (const float2*)(smc + ODL);
            float s = 0.f;
            #pragma unroll
            for (int d2 = 0; d2 < 32; d2++) {
                const __half2 hh = bh2[d2];
                const float2 dv = dl2[d2];
                s = fmaf(__half2float(hh.x), dv.x, fmaf(__half2float(hh.y), dv.y, s));
            }
            ((float*)(smc + OEV))[tid] = s;
        }

        // Stage 1: AC = Qu @ K^T (log2 domain)
        float sacc[8][4];
        #pragma unroll
        for (int nt = 0; nt < 8; nt++)
            #pragma unroll
            for (int r = 0; r < 4; r++) sacc[nt][r] = 0.f;
        #pragma unroll
        for (int k = 0; k < 4; k++) {
            #pragma unroll
            for (int p = 0; p < 4; p++) {
                uint32_t kh4[4];
                ldsm_x4(kh4, b_addr(sb + OKH, p * 16, k * 16, lane, ATP));
                mma_fp16(sacc[2 * p],     qu[k], kh4);
                mma_fp16(sacc[2 * p + 1], qu[k], kh4 + 2);
            }
        }
        __syncthreads();   // K reads done; EV visible

        // prefetch K_{i+1}
        #pragma unroll
        for (int jj = 0; jj < 4; jj++) {
            const int f = tid + 128 * jj;
            const int row = f >> 3, ch = f & 7;
            cp_async16(sb + OKH + (uint32_t)((row * ATP + ch * 8) * 2),
                       g_k16 + ((size_t)(s0n + row) * B_DIM + b) * C_DIM + h * 64 + ch * 8, true);
        }
        cp_commit();

        // Stage 2: windowed G = Qu @ band^T (5 p-tiles)
        float gacc[10][4];
        #pragma unroll
        for (int nt = 0; nt < 10; nt++)
            #pragma unroll
            for (int r = 0; r < 4; r++) gacc[nt][r] = 0.f;
        #pragma unroll
        for (int k = 0; k < 4; k++) {
            #pragma unroll
            for (int p = 0; p < 5; p++) {
                const int basep = (off + cbase + p * 16) & 127;
                uint32_t bh4[4];
                ldsm_x4(bh4, b_addr(sb + OBH, basep, k * 16, lane, ATP));
                mma_fp16(gacc[2 * p],     qu[k], bh4);
                mma_fp16(gacc[2 * p + 1], qu[k], bh4 + 2);
            }
        }
        {
            float* BD = (float*)(smc + OPH);
            const float* EV = (const float*)(smc + OEV);
            #pragma unroll
            for (int nt = 0; nt < 10; nt++)
                #pragma unroll
                for (int r2 = 0; r2 < 2; r2++) {
                    const int t = row0g + 8 * r2;
                    #pragma unroll
                    for (int cc = 0; cc < 2; cc++) {
                        const int c = cbase + nt * 8 + 2 * tg + cc;
                        const int s = c - 63 + t;
                        if (s >= 0 && s < 64)
                            BD[t * 68 + s] = gacc[nt][r2 * 2 + cc] + EV[c];
                    }
                }
        }
        __syncthreads();   // band reads done (before band prefetch); BD visible

        // prefetch band_{i+1}: 64 new p-rows
        #pragma unroll
        for (int jj = 0; jj < 4; jj++) {
            const int f = tid + 128 * jj;
            const int row = f >> 3, ch = f & 7;
            const int pr = wnx + 63 + row;
            const int slot = pr & 127;
            cp_async16(sb + OBH + (uint32_t)((slot * ATP + ch * 8) * 2),
                       g_p16 + (size_t)pr * C_DIM + h * 64 + ch * 8, true);
        }
        cp_commit();

        // Stage 3: P = 2^(ac + bd), pairwise in fp16
        const float* BD = (const float*)(smc + OPH);
        uint32_t pv2[16];
        #pragma unroll
        for (int nt = 0; nt < 8; nt++)
            #pragma unroll
            for (int r2 = 0; r2 < 2; r2++) {
                const int t = row0g + 8 * r2;
                const int s = nt * 8 + 2 * tg;
                float a0 = sacc[nt][r2 * 2]     + BD[t * 68 + s];
                float a1 = sacc[nt][r2 * 2 + 1] + BD[t * 68 + s + 1];
                a0 = fminf(a0, 14.4f);
                a1 = fminf(a1, 14.4f);
                uint32_t h2;
                asm("cvt.rn.f16x2.f32 %0, %1, %2;" : "=r"(h2) : "f"(a1), "f"(a0));
                asm("ex2.approx.f16x2 %0, %1;" : "=r"(h2) : "r"(h2));
                pv2[nt * 2 + r2] = h2;
            }
        __syncthreads();   // MANDATORY: BD aliases the P tile across warps
        {
            __half* Ph = (__half*)(smc + OPH);
            #pragma unroll
            for (int nt = 0; nt < 8; nt++)
                #pragma unroll
                for (int r2 = 0; r2 < 2; r2++) {
                    const int t = row0g + 8 * r2;
                    const int s = nt * 8 + 2 * tg;
                    *(uint32_t*)(Ph + (size_t)(t * ATP + s)) = pv2[nt * 2 + r2];
                }
        }
        cp_wait<2>();      // V_i arrived
        __syncthreads();   // P + V visible

        // Stage 4: O += P @ V; l += P @ 1 (ones-B MMA, no ldsm)
        #pragma unroll
        for (int k = 0; k < 4; k++) {
            uint32_t aph[4];
            ldsm_x4(aph, a_addr(sb + OPH, row0w, k * 16, lane, ATP));
            mma_fp16(lacc, aph, bones);
            #pragma unroll
            for (int p = 0; p < 4; p++) {
                uint32_t vh4[4];
                ldsm_x4t(vh4, a_addr(sb + OVH, k * 16, p * 16, lane, ATP));
                mma_fp16(oacc[2 * p],     aph, vh4);
                mma_fp16(oacc[2 * p + 1], aph, vh4 + 2);
            }
        }
        __syncthreads();   // V reads done

        // prefetch V_{i+1}
        #pragma unroll
        for (int jj = 0; jj < 4; jj++) {
            const int f = tid + 128 * jj;
            const int row = f >> 3, ch = f & 7;
            cp_async16(sb + OVH + (uint32_t)((row * ATP + ch * 8) * 2),
                       g_v16 + ((size_t)(s0n + row) * B_DIM + b) * C_DIM + h * 64 + ch * 8, true);
        }
        cp_commit();
    }
    cp_wait<0>();

    // Row sums came straight out of the ones-B MMA (replicated across cols).
    const float inv0 = 1.f / lacc[0];
    const float inv1 = 1.f / lacc[2];

    #pragma unroll
    for (int nt = 0; nt < 8; nt++) {
        const int col = h * 64 + nt * 8 + 2 * tg;
        const size_t o0 = ((size_t)(t0 + row0g) * B_DIM + b) * C_DIM + col;
        const size_t o1 = ((size_t)(t0 + row0g + 8) * B_DIM + b) * C_DIM + col;
        *(__half2*)(g_x16 + o0) =
            __halves2half2(__float2half_rn(oacc[nt][0] * inv0),
                           __float2half_rn(oacc[nt][1] * inv0));
        *(__half2*)(g_x16 + o1) =
            __halves2half2(__float2half_rn(oacc[nt][2] * inv1),
                           __float2half_rn(oacc[nt][3] * inv1));
    }
}

// ---------------------------------------------------------------------------
// Launch
// ---------------------------------------------------------------------------
extern "C" void kernel_launch(void* const* d_in, const int* in_sizes, int n_in,
                              void* d_out, int out_size)
{
    const float* query   = (const float*)d_in[0];
    const float* key     = (const float*)d_in[1];
    const float* value   = (const float*)d_in[2];
    const float* pos_emb = (const float*)d_in[3];
    const float* Wq      = (const float*)d_in[4];
    const float* bq      = (const float*)d_in[5];
    const float* Wk      = (const float*)d_in[6];
    const float* bk      = (const float*)d_in[7];
    const float* Wv      = (const float*)d_in[8];
    const float* bv      = (const float*)d_in[9];
    const float* Wp      = (const float*)d_in[10];
    const float* Wo      = (const float*)d_in[11];
    const float* bo      = (const float*)d_in[12];
    const float* pbu     = (const float*)d_in[13];
    const float* pbv     = (const float*)d_in[14];
    float* out = (float*)d_out;

    cudaFuncSetAttribute(proj_mega, cudaFuncAttributeMaxDynamicSharedMemorySize, FSM_BYTES);
    cudaFuncSetAttribute(gemm_out,  cudaFuncAttributeMaxDynamicSharedMemorySize, FSM_BYTES);
    cudaFuncSetAttribute(attn_f16,  cudaFuncAttributeMaxDynamicSharedMemorySize, ATT_BYTES);

    split_all<<<19455, 256>>>((const float4*)Wq, (const float4*)Wk, (const float4*)Wv,
                              (const float4*)Wp, (const float4*)Wo,
                              (const float4*)query, (const float4*)key,
                              (const float4*)value, (const float4*)pos_emb);

    proj_mega<<<896, 256, FSM_BYTES>>>(bq, bk, bv, pbu);
    attn_f16<<<dim3(16, 64), 128, ATT_BYTES>>>(pbu, pbv);
    gemm_out<<<256, 256, FSM_BYTES>>>(bo, out);
}